// round 3
// baseline (speedup 1.0000x reference)
#include <cuda_runtime.h>

#define TTOK   2048
#define DMODEL 1024
#define DFS    2048
#define DFE    512
#define NEXP   8
#define MAXPE  2048

typedef unsigned long long u64;

// ---------------- scratch (device globals; no allocation allowed) ----------
__device__ float g_gu1 [TTOK * 2 * DFS];            // 32MB  [t][gate 0:2048 | up 2048:4096]
__device__ float g_act1[TTOK * DFS];                // 16MB
__device__ float g_sh  [TTOK * DMODEL];             // 8MB   shared MLP output
__device__ float g_gu2 [NEXP * MAXPE * 2 * DFE];    // 64MB  [slot][gate 0:512 | up 512:1024]
__device__ float g_act2[NEXP * MAXPE * DFE];        // 32MB
__device__ float g_eo  [NEXP * MAXPE * DMODEL];     // 64MB
__device__ int   g_cnt [NEXP];
__device__ int   g_tok [NEXP * MAXPE];
__device__ int   g_slot0[TTOK];
__device__ int   g_slot1[TTOK];
__device__ float g_c0[TTOK];
__device__ float g_c1[TTOK];
__device__ float g_cs[TTOK];

// ---------------- f32x2 packed FMA helpers ---------------------------------
__device__ __forceinline__ u64 pack_dup(float v) {
    union { float2 f; u64 u; } cv;
    cv.f.x = v; cv.f.y = v;
    return cv.u;
}
__device__ __forceinline__ float2 unpack2(u64 v) {
    union { float2 f; u64 u; } cv;
    cv.u = v;
    return cv.f;
}
__device__ __forceinline__ void fma2(u64 &c, u64 a, u64 b) {
    asm("fma.rn.f32x2 %0, %1, %2, %0;" : "+l"(c) : "l"(a), "l"(b));
}

// ---------------- tiny kernels ---------------------------------------------
__global__ void k_zero() {
    if (threadIdx.x < NEXP) g_cnt[threadIdx.x] = 0;
}

// one warp per token: logits[8], top-2, softmax, fold alpha, claim slots
__global__ void k_router(const float* __restrict__ x,
                         const float* __restrict__ rw,
                         const float* __restrict__ alpha) {
    int warp = (blockIdx.x * blockDim.x + threadIdx.x) >> 5;
    int lane = threadIdx.x & 31;
    if (warp >= TTOK) return;
    const float* xr = x + (size_t)warp * DMODEL;
    float acc[NEXP];
#pragma unroll
    for (int e = 0; e < NEXP; e++) acc[e] = 0.f;
    for (int d = lane; d < DMODEL; d += 32) {
        float xv = xr[d];
#pragma unroll
        for (int e = 0; e < NEXP; e++) acc[e] += xv * rw[e * DMODEL + d];
    }
#pragma unroll
    for (int e = 0; e < NEXP; e++)
#pragma unroll
        for (int off = 16; off; off >>= 1)
            acc[e] += __shfl_xor_sync(0xffffffffu, acc[e], off);
    if (lane == 0) {
        int e0 = 0; float v0 = acc[0];
#pragma unroll
        for (int e = 1; e < NEXP; e++) if (acc[e] > v0) { v0 = acc[e]; e0 = e; }
        int e1 = -1; float v1 = -3.4e38f;
#pragma unroll
        for (int e = 0; e < NEXP; e++) if (e != e0 && acc[e] > v1) { v1 = acc[e]; e1 = e; }
        float w0 = 1.f / (1.f + __expf(v1 - v0));
        float w1 = 1.f - w0;
        float c0 = w0 * alpha[e0];
        float c1 = w1 * alpha[e1];
        int p0 = atomicAdd(&g_cnt[e0], 1);
        int p1 = atomicAdd(&g_cnt[e1], 1);
        g_tok[e0 * MAXPE + p0] = warp;
        g_tok[e1 * MAXPE + p1] = warp;
        g_slot0[warp] = e0 * MAXPE + p0;
        g_slot1[warp] = e1 * MAXPE + p1;
        g_c0[warp] = c0;
        g_c1[warp] = c1;
        g_cs[warp] = 1.f - c0 - c1;
    }
}

__device__ __forceinline__ float4 silu_mul4(float4 g, float4 u) {
    float4 r;
    r.x = g.x * u.x / (1.f + __expf(-g.x));
    r.y = g.y * u.y / (1.f + __expf(-g.y));
    r.z = g.z * u.z / (1.f + __expf(-g.z));
    r.w = g.w * u.w / (1.f + __expf(-g.w));
    return r;
}

__global__ void k_swiglu1() {
    int i = blockIdx.x * blockDim.x + threadIdx.x;   // over TTOK*DFS/4
    int t = i / (DFS / 4);
    int f = i % (DFS / 4);
    const float* row = g_gu1 + (size_t)t * (2 * DFS);
    float4 g = *(const float4*)(row + f * 4);
    float4 u = *(const float4*)(row + DFS + f * 4);
    *(float4*)&g_act1[(size_t)t * DFS + f * 4] = silu_mul4(g, u);
}

__global__ void k_swiglu2() {
    int e = blockIdx.y;
    int r = blockIdx.x;
    if (r >= g_cnt[e]) return;
    int c = threadIdx.x;                              // 128 threads = DFE/4
    const float* row = g_gu2 + ((size_t)e * MAXPE + r) * (2 * DFE);
    float4 g = *(const float4*)(row + c * 4);
    float4 u = *(const float4*)(row + DFE + c * 4);
    *(float4*)&g_act2[((size_t)e * MAXPE + r) * DFE + c * 4] = silu_mul4(g, u);
}

__global__ void k_combine(float* __restrict__ out) {
    int t = blockIdx.x;
    int c = threadIdx.x;                              // 256 = DMODEL/4
    float cs = g_cs[t], c0 = g_c0[t], c1 = g_c1[t];
    size_t s0 = (size_t)g_slot0[t] * DMODEL;
    size_t s1 = (size_t)g_slot1[t] * DMODEL;
    float4 sh = *(const float4*)&g_sh[(size_t)t * DMODEL + c * 4];
    float4 a  = *(const float4*)&g_eo[s0 + c * 4];
    float4 b  = *(const float4*)&g_eo[s1 + c * 4];
    float4 o;
    o.x = cs * sh.x + c0 * a.x + c1 * b.x;
    o.y = cs * sh.y + c0 * a.y + c1 * b.y;
    o.z = cs * sh.z + c0 * a.z + c1 * b.z;
    o.w = cs * sh.w + c0 * a.w + c1 * b.w;
    *(float4*)&out[(size_t)t * DMODEL + c * 4] = o;
}

// ---------------- SIMT GEMM core: C[m,n] = (scale[n]) * sum_k A[m,k]*B[n,k] -
// 128x128 block tile, BK=8, 256 threads, 8x8 per-thread with f32x2 accumulators.
template<bool GATHER, bool QUANT>
__device__ __forceinline__ void gemm_core(
    const float* __restrict__ Af, const int* __restrict__ list,
    int Mcnt, int K,
    const float* __restrict__ Bf, const int* __restrict__ Bq,
    const float* __restrict__ scale,
    float* __restrict__ C, int ldc, int m0)
{
    __shared__ float As[8][132];
    __shared__ float Bs[8][132];
    const int tid = threadIdx.x;
    const int lr = tid >> 1;              // load row within tile (0..127)
    const int lk = (tid & 1) << 2;        // k sub-offset (0 or 4)
    const int tm = (tid >> 4) << 3;       // compute row base (0..120)
    const int tn = (tid & 15) << 3;       // compute col base (0..120)

    const float* arow;
    bool avalid;
    if (GATHER) {
        int ri = m0 + lr;
        avalid = (ri < Mcnt);
        arow = Af + (size_t)(avalid ? list[ri] : 0) * K;
    } else {
        avalid = true;
        arow = Af + (size_t)(m0 + lr) * K;
    }
    const float* browf = QUANT ? (const float*)0 : (Bf + (size_t)lr * K);
    const int*   browq = QUANT ? (Bq + (size_t)lr * K) : (const int*)0;

    u64 acc[4][8];
#pragma unroll
    for (int i = 0; i < 4; i++)
#pragma unroll
        for (int j = 0; j < 8; j++) acc[i][j] = 0ull;

    for (int k0 = 0; k0 < K; k0 += 8) {
        float4 a4 = make_float4(0.f, 0.f, 0.f, 0.f);
        if (avalid) a4 = *(const float4*)(arow + k0 + lk);
        float4 b4;
        if (QUANT) {
            int4 q = *(const int4*)(browq + k0 + lk);
            b4 = make_float4((float)q.x, (float)q.y, (float)q.z, (float)q.w);
        } else {
            b4 = *(const float4*)(browf + k0 + lk);
        }
        __syncthreads();
        As[lk + 0][lr] = a4.x; As[lk + 1][lr] = a4.y;
        As[lk + 2][lr] = a4.z; As[lk + 3][lr] = a4.w;
        Bs[lk + 0][lr] = b4.x; Bs[lk + 1][lr] = b4.y;
        Bs[lk + 2][lr] = b4.z; Bs[lk + 3][lr] = b4.w;
        __syncthreads();
#pragma unroll
        for (int kk = 0; kk < 8; kk++) {
            ulonglong2 aP = *(const ulonglong2*)&As[kk][tm];
            ulonglong2 aQ = *(const ulonglong2*)&As[kk][tm + 4];
            u64 ap[4] = {aP.x, aP.y, aQ.x, aQ.y};
            float4 bA = *(const float4*)&Bs[kk][tn];
            float4 bB = *(const float4*)&Bs[kk][tn + 4];
            u64 bd[8];
            bd[0] = pack_dup(bA.x); bd[1] = pack_dup(bA.y);
            bd[2] = pack_dup(bA.z); bd[3] = pack_dup(bA.w);
            bd[4] = pack_dup(bB.x); bd[5] = pack_dup(bB.y);
            bd[6] = pack_dup(bB.z); bd[7] = pack_dup(bB.w);
#pragma unroll
            for (int i = 0; i < 4; i++)
#pragma unroll
                for (int j = 0; j < 8; j++) fma2(acc[i][j], ap[i], bd[j]);
        }
    }

    float sc[8];
    if (QUANT) {
        float4 s0 = *(const float4*)(scale + tn);
        float4 s1 = *(const float4*)(scale + tn + 4);
        sc[0] = s0.x; sc[1] = s0.y; sc[2] = s0.z; sc[3] = s0.w;
        sc[4] = s1.x; sc[5] = s1.y; sc[6] = s1.z; sc[7] = s1.w;
    }

#pragma unroll
    for (int i = 0; i < 4; i++) {
        float o0[8], o1[8];
#pragma unroll
        for (int j = 0; j < 8; j++) {
            float2 v = unpack2(acc[i][j]);
            o0[j] = QUANT ? v.x * sc[j] : v.x;
            o1[j] = QUANT ? v.y * sc[j] : v.y;
        }
        int r = m0 + tm + 2 * i;
        if (r < Mcnt) {
            *(float4*)(C + (size_t)r * ldc + tn)     = make_float4(o0[0], o0[1], o0[2], o0[3]);
            *(float4*)(C + (size_t)r * ldc + tn + 4) = make_float4(o0[4], o0[5], o0[6], o0[7]);
        }
        if (r + 1 < Mcnt) {
            *(float4*)(C + (size_t)(r + 1) * ldc + tn)     = make_float4(o1[0], o1[1], o1[2], o1[3]);
            *(float4*)(C + (size_t)(r + 1) * ldc + tn + 4) = make_float4(o1[4], o1[5], o1[6], o1[7]);
        }
    }
}

// shared gate+up: M=2048, N=4096 (gate|up stacked), K=1024 -> g_gu1
__global__ __launch_bounds__(256, 2)
void k_gemm_gateup(const float* __restrict__ x,
                   const float* __restrict__ gw,
                   const float* __restrict__ uw) {
    int n0 = blockIdx.x * 128;
    int m0 = blockIdx.y * 128;
    const float* B = (n0 < DFS) ? (gw + (size_t)n0 * DMODEL)
                                : (uw + (size_t)(n0 - DFS) * DMODEL);
    gemm_core<false, false>(x, 0, TTOK, DMODEL, B, 0, 0, g_gu1 + n0, 2 * DFS, m0);
}

// shared down: M=2048, N=1024, K=2048 -> g_sh
__global__ __launch_bounds__(256, 2)
void k_gemm_down(const float* __restrict__ dw) {
    int n0 = blockIdx.x * 128;
    int m0 = blockIdx.y * 128;
    gemm_core<false, false>(g_act1, 0, TTOK, DFS,
                            dw + (size_t)n0 * DFS, 0, 0, g_sh + n0, DMODEL, m0);
}

// expert gate+up: per expert, gathered rows of x, N=1024 (gate|up), K=1024 -> g_gu2
__global__ __launch_bounds__(256, 2)
void k_gemm_expert_gu(const float* __restrict__ x,
                      const int* __restrict__ gate_q, const int* __restrict__ up_q,
                      const float* __restrict__ gate_s, const float* __restrict__ up_s) {
    int e = blockIdx.z;
    int cnt = g_cnt[e];
    int m0 = blockIdx.y * 128;
    if (m0 >= cnt) return;
    int n0 = blockIdx.x * 128;
    const int* Bq; const float* s;
    if (n0 < DFE) { Bq = gate_q + ((size_t)e * DFE + n0) * DMODEL;       s = gate_s + e * DFE + n0; }
    else          { Bq = up_q   + ((size_t)e * DFE + (n0 - DFE)) * DMODEL; s = up_s  + e * DFE + (n0 - DFE); }
    gemm_core<true, true>(x, g_tok + e * MAXPE, cnt, DMODEL,
                          0, Bq, s,
                          g_gu2 + (size_t)e * MAXPE * (2 * DFE) + n0, 2 * DFE, m0);
}

// expert down: per expert, M=cnt, N=1024, K=512 -> g_eo
__global__ __launch_bounds__(256, 2)
void k_gemm_expert_down(const int* __restrict__ down_q,
                        const float* __restrict__ down_s) {
    int e = blockIdx.z;
    int cnt = g_cnt[e];
    int m0 = blockIdx.y * 128;
    if (m0 >= cnt) return;
    int n0 = blockIdx.x * 128;
    gemm_core<false, true>(g_act2 + (size_t)e * MAXPE * DFE, 0, cnt, DFE,
                           0, down_q + ((size_t)e * DMODEL + n0) * DFE,
                           down_s + e * DMODEL + n0,
                           g_eo + (size_t)e * MAXPE * DMODEL + n0, DMODEL, m0);
}

// ---------------- launch ----------------------------------------------------
extern "C" void kernel_launch(void* const* d_in, const int* in_sizes, int n_in,
                              void* d_out, int out_size) {
    const float *x, *rw, *shg, *shu, *shd, *gs, *us, *ds, *al;
    const int *gq, *uq, *dq;
    if (in_sizes[0] == NEXP) {
        // alphabetical order: alpha, down_q, down_s, gate_q, gate_s, router_weight,
        //                     sh_down_w, sh_gate_w, sh_up_w, top_k, up_q, up_s, x
        al  = (const float*)d_in[0];
        dq  = (const int*)  d_in[1];
        ds  = (const float*)d_in[2];
        gq  = (const int*)  d_in[3];
        gs  = (const float*)d_in[4];
        rw  = (const float*)d_in[5];
        shd = (const float*)d_in[6];
        shg = (const float*)d_in[7];
        shu = (const float*)d_in[8];
        uq  = (const int*)  d_in[10];
        us  = (const float*)d_in[11];
        x   = (const float*)d_in[12];
    } else {
        // insertion order per setup_inputs()
        x   = (const float*)d_in[0];
        rw  = (const float*)d_in[1];
        shg = (const float*)d_in[2];
        shu = (const float*)d_in[3];
        shd = (const float*)d_in[4];
        gs  = (const float*)d_in[5];
        us  = (const float*)d_in[6];
        ds  = (const float*)d_in[7];
        al  = (const float*)d_in[8];
        gq  = (const int*)  d_in[9];
        uq  = (const int*)  d_in[10];
        dq  = (const int*)  d_in[11];
    }
    float* out = (float*)d_out;

    k_zero<<<1, 32>>>();
    k_router<<<TTOK / 8, 256>>>(x, rw, al);
    k_gemm_gateup<<<dim3(32, 16, 1), 256>>>(x, shg, shu);
    k_swiglu1<<<(TTOK * DFS / 4) / 256, 256>>>();
    k_gemm_down<<<dim3(8, 16, 1), 256>>>(shd);
    k_gemm_expert_gu<<<dim3(8, 16, NEXP), 256>>>(x, gq, uq, gs, us);
    k_swiglu2<<<dim3(MAXPE, NEXP, 1), 128>>>();
    k_gemm_expert_down<<<dim3(8, 16, NEXP), 256>>>(dq, ds);
    k_combine<<<TTOK, 256>>>(out);
}

// round 7
// speedup vs baseline: 2.0065x; 2.0065x over previous
#include <cuda_runtime.h>
#include <cstdint>

#define TTOK   2048
#define DMODEL 1024
#define DFS    2048
#define DFE    512
#define NEXP   8
#define MAXPE  2048

typedef unsigned long long u64;

// ---------------- scratch (device globals; no allocation allowed) ----------
__device__ float g_xr  [TTOK * DMODEL];             // tf32-rounded x
__device__ float g_wr  [3 * DFS * DMODEL];          // rounded shg | shu | shd
__device__ float g_gu1 [TTOK * 2 * DFS];            // [t][gate 0:2048 | up 2048:4096]
__device__ float g_act1[TTOK * DFS];
__device__ float g_sh  [TTOK * DMODEL];
__device__ float g_gu2 [NEXP * MAXPE * 2 * DFE];    // [slot][gate 0:512 | up 512:1024]
__device__ float g_act2[NEXP * MAXPE * DFE];
__device__ float g_eo  [NEXP * MAXPE * DMODEL];
__device__ int   g_cnt [NEXP];
__device__ int   g_tok [NEXP * MAXPE];
__device__ int   g_slot0[TTOK];
__device__ int   g_slot1[TTOK];
__device__ float g_c0[TTOK];
__device__ float g_c1[TTOK];
__device__ float g_cs[TTOK];

#define SHU_OFF (DFS * DMODEL)
#define SHD_OFF (2 * DFS * DMODEL)

// ---------------- helpers ---------------------------------------------------
__device__ __forceinline__ float cvt_rna_tf32(float x) {
    uint32_t r;
    asm("cvt.rna.tf32.f32 %0, %1;" : "=r"(r) : "f"(x));
    return __uint_as_float(r);
}
__device__ __forceinline__ void cp16(uint32_t dst, const void* src) {
    asm volatile("cp.async.cg.shared.global [%0], [%1], 16;" :: "r"(dst), "l"(src));
}
__device__ __forceinline__ void cp_commit() {
    asm volatile("cp.async.commit_group;" ::: "memory");
}
__device__ __forceinline__ void cp_wait1() {
    asm volatile("cp.async.wait_group 1;" ::: "memory");
}
__device__ __forceinline__ void cp_wait0() {
    asm volatile("cp.async.wait_group 0;" ::: "memory");
}
__device__ __forceinline__ void mma_tf32(float* c, const uint32_t* a,
                                         uint32_t b0, uint32_t b1) {
    asm volatile(
        "mma.sync.aligned.m16n8k8.row.col.f32.tf32.tf32.f32 "
        "{%0,%1,%2,%3}, {%4,%5,%6,%7}, {%8,%9}, {%0,%1,%2,%3};"
        : "+f"(c[0]), "+f"(c[1]), "+f"(c[2]), "+f"(c[3])
        : "r"(a[0]), "r"(a[1]), "r"(a[2]), "r"(a[3]), "r"(b0), "r"(b1));
}

#define SMEM_DYN 65536   // 2 bufs x (A 16KB + B 16KB)

// ---------------- mma.sync tf32 GEMM ----------------------------------------
// C[m,n] = scale[n] * sum_k A[m,k] * B[n,k]; 128x128 tile, BK=32, 128 threads.
// smem float layout: buf*8192 + mat*4096 + row*32 + ((slot16 ^ (row&7))*4) + e
template<bool GATHER, bool QUANT>
__device__ __forceinline__ void gemm_mma(
    const float* __restrict__ Af, const int* __restrict__ list,
    int Mcnt, int K,
    const float* __restrict__ Bf, const int* __restrict__ Bq,
    const float* __restrict__ scale,
    float* __restrict__ C, int ldc, int m0)
{
    extern __shared__ float smf[];
    const int tid  = threadIdx.x;
    const int wid  = tid >> 5;
    const int lane = tid & 31;
    const int g    = lane >> 2;   // group id (0..7)
    const int t    = lane & 3;    // thread-in-group (0..3)
    const int warpM = (wid & 1) * 64;
    const int warpN = (wid >> 1) * 64;

    // per-thread staging sources (row = tid)
    int ari = m0 + tid;
    int asrc_row;
    if (GATHER) asrc_row = list[(ari < Mcnt) ? ari : 0];
    else        asrc_row = (ari < Mcnt) ? ari : (Mcnt - 1);
    const float* arow = Af + (size_t)asrc_row * K;
    const float* browf = QUANT ? (const float*)0 : (Bf + (size_t)tid * K);
    const int*   browq = QUANT ? (Bq + (size_t)tid * K) : (const int*)0;

    const int sw = (tid & 7);
    uint32_t sm_u32 = (uint32_t)__cvta_generic_to_shared(smf);
    const uint32_t aDst = sm_u32 + (uint32_t)(tid * 32) * 4u;
    const uint32_t bDst = aDst + 4096u * 4u;

    // fragment offsets (floats)
    int offA[8], offB[8];
#pragma unroll
    for (int m = 0; m < 4; m++) {
        offA[2 * m]     = (warpM + m * 16 + g) * 32 + t;
        offA[2 * m + 1] = (warpM + m * 16 + 8 + g) * 32 + t;
    }
#pragma unroll
    for (int n = 0; n < 8; n++)
        offB[n] = 4096 + (warpN + n * 8 + g) * 32 + t;

    float acc[4][8][4];
#pragma unroll
    for (int m = 0; m < 4; m++)
#pragma unroll
        for (int n = 0; n < 8; n++)
#pragma unroll
            for (int q = 0; q < 4; q++) acc[m][n][q] = 0.f;

    const int nch = K >> 5;

    // ---- stage chunk 0
    {
        const int k0 = 0;
#pragma unroll
        for (int c = 0; c < 8; c++)
            cp16(aDst + (uint32_t)((c ^ sw) * 16), arow + k0 + c * 4);
        if (QUANT) {
            float* bd = smf + 4096 + tid * 32;
#pragma unroll
            for (int c = 0; c < 8; c++) {
                int4 q = *(const int4*)(browq + k0 + c * 4);
                float4 v = make_float4((float)q.x, (float)q.y, (float)q.z, (float)q.w);
                *(float4*)(bd + (c ^ sw) * 4) = v;
            }
        } else {
#pragma unroll
            for (int c = 0; c < 8; c++)
                cp16(bDst + (uint32_t)((c ^ sw) * 16), browf + k0 + c * 4);
        }
        cp_commit();
    }

    for (int ch = 0; ch < nch; ch++) {
        // ---- stage next chunk into other buffer
        if (ch + 1 < nch) {
            const int buf = (ch + 1) & 1;
            const int k0 = (ch + 1) << 5;
            const uint32_t ao = aDst + (uint32_t)(buf * 8192) * 4u;
#pragma unroll
            for (int c = 0; c < 8; c++)
                cp16(ao + (uint32_t)((c ^ sw) * 16), arow + k0 + c * 4);
            if (QUANT) {
                float* bd = smf + buf * 8192 + 4096 + tid * 32;
#pragma unroll
                for (int c = 0; c < 8; c++) {
                    int4 q = *(const int4*)(browq + k0 + c * 4);
                    float4 v = make_float4((float)q.x, (float)q.y, (float)q.z, (float)q.w);
                    *(float4*)(bd + (c ^ sw) * 4) = v;
                }
            } else {
                const uint32_t bo = bDst + (uint32_t)(buf * 8192) * 4u;
#pragma unroll
                for (int c = 0; c < 8; c++)
                    cp16(bo + (uint32_t)((c ^ sw) * 16), browf + k0 + c * 4);
            }
            cp_commit();
            cp_wait1();
        } else {
            cp_wait0();
        }
        __syncthreads();

        // ---- compute on buf = ch&1 : 4 ksteps of K=8
        const float* bb = smf + (ch & 1) * 8192;
#pragma unroll
        for (int j = 0; j < 4; j++) {
            const int sl0 = ((2 * j) ^ g) * 4;
            const int sl1 = ((2 * j + 1) ^ g) * 4;
            uint32_t af[4][4];
#pragma unroll
            for (int m = 0; m < 4; m++) {
                af[m][0] = *(const uint32_t*)&bb[offA[2 * m]     + sl0];
                af[m][1] = *(const uint32_t*)&bb[offA[2 * m + 1] + sl0];
                af[m][2] = *(const uint32_t*)&bb[offA[2 * m]     + sl1];
                af[m][3] = *(const uint32_t*)&bb[offA[2 * m + 1] + sl1];
            }
#pragma unroll
            for (int n = 0; n < 8; n++) {
                uint32_t b0 = *(const uint32_t*)&bb[offB[n] + sl0];
                uint32_t b1 = *(const uint32_t*)&bb[offB[n] + sl1];
#pragma unroll
                for (int m = 0; m < 4; m++)
                    mma_tf32(acc[m][n], af[m], b0, b1);
            }
        }
        __syncthreads();
    }

    // ---- epilogue
#pragma unroll
    for (int n = 0; n < 8; n++) {
        const int col = warpN + n * 8 + 2 * t;
        float s0 = 1.f, s1 = 1.f;
        if (QUANT) {
            float2 sc = *(const float2*)(scale + col);
            s0 = sc.x; s1 = sc.y;
        }
#pragma unroll
        for (int m = 0; m < 4; m++) {
            int r = m0 + warpM + m * 16 + g;
            if (r < Mcnt) {
                float2 v = make_float2(acc[m][n][0] * s0, acc[m][n][1] * s1);
                *(float2*)(C + (size_t)r * ldc + col) = v;
            }
            if (r + 8 < Mcnt) {
                float2 v = make_float2(acc[m][n][2] * s0, acc[m][n][3] * s1);
                *(float2*)(C + (size_t)(r + 8) * ldc + col) = v;
            }
        }
    }
}

// ---------------- GEMM kernel wrappers --------------------------------------
__global__ __launch_bounds__(128, 2)
void k_gemm_gateup() {
    int n0 = blockIdx.x * 128;
    int m0 = blockIdx.y * 128;
    // shg rows [0,2048) then shu rows [0,2048) are contiguous in g_wr
    gemm_mma<false, false>(g_xr, 0, TTOK, DMODEL,
                           g_wr + (size_t)n0 * DMODEL, 0, 0,
                           g_gu1 + n0, 2 * DFS, m0);
}

__global__ __launch_bounds__(128, 2)
void k_gemm_down() {
    int n0 = blockIdx.x * 128;
    int m0 = blockIdx.y * 128;
    gemm_mma<false, false>(g_act1, 0, TTOK, DFS,
                           g_wr + SHD_OFF + (size_t)n0 * DFS, 0, 0,
                           g_sh + n0, DMODEL, m0);
}

__global__ __launch_bounds__(128, 2)
void k_gemm_expert_gu(const int* __restrict__ gate_q, const int* __restrict__ up_q,
                      const float* __restrict__ gate_s, const float* __restrict__ up_s) {
    int e = blockIdx.z;
    int cnt = g_cnt[e];
    int m0 = blockIdx.y * 128;
    if (m0 >= cnt) return;
    int n0 = blockIdx.x * 128;
    const int* Bq; const float* s;
    if (n0 < DFE) { Bq = gate_q + ((size_t)e * DFE + n0) * DMODEL;         s = gate_s + e * DFE + n0; }
    else          { Bq = up_q   + ((size_t)e * DFE + (n0 - DFE)) * DMODEL; s = up_s   + e * DFE + (n0 - DFE); }
    gemm_mma<true, true>(g_xr, g_tok + e * MAXPE, cnt, DMODEL,
                         0, Bq, s,
                         g_gu2 + (size_t)e * MAXPE * (2 * DFE) + n0, 2 * DFE, m0);
}

__global__ __launch_bounds__(128, 2)
void k_gemm_expert_down(const int* __restrict__ down_q,
                        const float* __restrict__ down_s) {
    int e = blockIdx.z;
    int cnt = g_cnt[e];
    int m0 = blockIdx.y * 128;
    if (m0 >= cnt) return;
    int n0 = blockIdx.x * 128;
    gemm_mma<false, true>(g_act2 + (size_t)e * MAXPE * DFE, 0, cnt, DFE,
                          0, down_q + ((size_t)e * DMODEL + n0) * DFE,
                          down_s + e * DMODEL + n0,
                          g_eo + (size_t)e * MAXPE * DMODEL + n0, DMODEL, m0);
}

// ---------------- small kernels ---------------------------------------------
__global__ void k_zero() {
    if (threadIdx.x < NEXP) g_cnt[threadIdx.x] = 0;
}

__global__ void k_round(const float* __restrict__ s, float* __restrict__ d, int n4) {
    int i = blockIdx.x * blockDim.x + threadIdx.x;
    if (i >= n4) return;
    float4 v = ((const float4*)s)[i];
    v.x = cvt_rna_tf32(v.x); v.y = cvt_rna_tf32(v.y);
    v.z = cvt_rna_tf32(v.z); v.w = cvt_rna_tf32(v.w);
    ((float4*)d)[i] = v;
}

__global__ void k_router(const float* __restrict__ x,
                         const float* __restrict__ rw,
                         const float* __restrict__ alpha) {
    int warp = (blockIdx.x * blockDim.x + threadIdx.x) >> 5;
    int lane = threadIdx.x & 31;
    if (warp >= TTOK) return;
    const float* xr = x + (size_t)warp * DMODEL;
    float acc[NEXP];
#pragma unroll
    for (int e = 0; e < NEXP; e++) acc[e] = 0.f;
    for (int d = lane; d < DMODEL; d += 32) {
        float xv = xr[d];
#pragma unroll
        for (int e = 0; e < NEXP; e++) acc[e] += xv * rw[e * DMODEL + d];
    }
#pragma unroll
    for (int e = 0; e < NEXP; e++)
#pragma unroll
        for (int off = 16; off; off >>= 1)
            acc[e] += __shfl_xor_sync(0xffffffffu, acc[e], off);
    if (lane == 0) {
        int e0 = 0; float v0 = acc[0];
#pragma unroll
        for (int e = 1; e < NEXP; e++) if (acc[e] > v0) { v0 = acc[e]; e0 = e; }
        int e1 = -1; float v1 = -3.4e38f;
#pragma unroll
        for (int e = 0; e < NEXP; e++) if (e != e0 && acc[e] > v1) { v1 = acc[e]; e1 = e; }
        float w0 = 1.f / (1.f + __expf(v1 - v0));
        float w1 = 1.f - w0;
        float c0 = w0 * alpha[e0];
        float c1 = w1 * alpha[e1];
        int p0 = atomicAdd(&g_cnt[e0], 1);
        int p1 = atomicAdd(&g_cnt[e1], 1);
        g_tok[e0 * MAXPE + p0] = warp;
        g_tok[e1 * MAXPE + p1] = warp;
        g_slot0[warp] = e0 * MAXPE + p0;
        g_slot1[warp] = e1 * MAXPE + p1;
        g_c0[warp] = c0;
        g_c1[warp] = c1;
        g_cs[warp] = 1.f - c0 - c1;
    }
}

__device__ __forceinline__ float4 silu_mul4_rnd(float4 g, float4 u) {
    float4 r;
    r.x = cvt_rna_tf32(g.x * u.x / (1.f + __expf(-g.x)));
    r.y = cvt_rna_tf32(g.y * u.y / (1.f + __expf(-g.y)));
    r.z = cvt_rna_tf32(g.z * u.z / (1.f + __expf(-g.z)));
    r.w = cvt_rna_tf32(g.w * u.w / (1.f + __expf(-g.w)));
    return r;
}

__global__ void k_swiglu1() {
    int i = blockIdx.x * blockDim.x + threadIdx.x;
    int t = i / (DFS / 4);
    int f = i % (DFS / 4);
    const float* row = g_gu1 + (size_t)t * (2 * DFS);
    float4 g = *(const float4*)(row + f * 4);
    float4 u = *(const float4*)(row + DFS + f * 4);
    *(float4*)&g_act1[(size_t)t * DFS + f * 4] = silu_mul4_rnd(g, u);
}

__global__ void k_swiglu2() {
    int e = blockIdx.y;
    int r = blockIdx.x;
    if (r >= g_cnt[e]) return;
    int c = threadIdx.x;
    const float* row = g_gu2 + ((size_t)e * MAXPE + r) * (2 * DFE);
    float4 g = *(const float4*)(row + c * 4);
    float4 u = *(const float4*)(row + DFE + c * 4);
    *(float4*)&g_act2[((size_t)e * MAXPE + r) * DFE + c * 4] = silu_mul4_rnd(g, u);
}

__global__ void k_combine(float* __restrict__ out) {
    int t = blockIdx.x;
    int c = threadIdx.x;
    float cs = g_cs[t], c0 = g_c0[t], c1 = g_c1[t];
    size_t s0 = (size_t)g_slot0[t] * DMODEL;
    size_t s1 = (size_t)g_slot1[t] * DMODEL;
    float4 sh = *(const float4*)&g_sh[(size_t)t * DMODEL + c * 4];
    float4 a  = *(const float4*)&g_eo[s0 + c * 4];
    float4 b  = *(const float4*)&g_eo[s1 + c * 4];
    float4 o;
    o.x = cs * sh.x + c0 * a.x + c1 * b.x;
    o.y = cs * sh.y + c0 * a.y + c1 * b.y;
    o.z = cs * sh.z + c0 * a.z + c1 * b.z;
    o.w = cs * sh.w + c0 * a.w + c1 * b.w;
    *(float4*)&out[(size_t)t * DMODEL + c * 4] = o;
}

// ---------------- launch ----------------------------------------------------
extern "C" void kernel_launch(void* const* d_in, const int* in_sizes, int n_in,
                              void* d_out, int out_size) {
    const float *x, *rw, *shg, *shu, *shd, *gs, *us, *ds, *al;
    const int *gq, *uq, *dq;
    if (in_sizes[0] == NEXP) {
        al  = (const float*)d_in[0];
        dq  = (const int*)  d_in[1];
        ds  = (const float*)d_in[2];
        gq  = (const int*)  d_in[3];
        gs  = (const float*)d_in[4];
        rw  = (const float*)d_in[5];
        shd = (const float*)d_in[6];
        shg = (const float*)d_in[7];
        shu = (const float*)d_in[8];
        uq  = (const int*)  d_in[10];
        us  = (const float*)d_in[11];
        x   = (const float*)d_in[12];
    } else {
        x   = (const float*)d_in[0];
        rw  = (const float*)d_in[1];
        shg = (const float*)d_in[2];
        shu = (const float*)d_in[3];
        shd = (const float*)d_in[4];
        gs  = (const float*)d_in[5];
        us  = (const float*)d_in[6];
        ds  = (const float*)d_in[7];
        al  = (const float*)d_in[8];
        gq  = (const int*)  d_in[9];
        uq  = (const int*)  d_in[10];
        dq  = (const int*)  d_in[11];
    }
    float* out = (float*)d_out;

    static int attr_done = 0;
    if (!attr_done) {
        cudaFuncSetAttribute(k_gemm_gateup,      cudaFuncAttributeMaxDynamicSharedMemorySize, SMEM_DYN);
        cudaFuncSetAttribute(k_gemm_down,        cudaFuncAttributeMaxDynamicSharedMemorySize, SMEM_DYN);
        cudaFuncSetAttribute(k_gemm_expert_gu,   cudaFuncAttributeMaxDynamicSharedMemorySize, SMEM_DYN);
        cudaFuncSetAttribute(k_gemm_expert_down, cudaFuncAttributeMaxDynamicSharedMemorySize, SMEM_DYN);
        attr_done = 1;
    }

    float* wr_base = 0;
    cudaGetSymbolAddress((void**)&wr_base, g_wr);
    float* xr_base = 0;
    cudaGetSymbolAddress((void**)&xr_base, g_xr);

    k_zero<<<1, 32>>>();
    k_router<<<TTOK / 8, 256>>>(x, rw, al);
    k_round<<<2048, 256>>>(x,   xr_base,            TTOK * DMODEL / 4);
    k_round<<<2048, 256>>>(shg, wr_base,            DFS * DMODEL / 4);
    k_round<<<2048, 256>>>(shu, wr_base + SHU_OFF,  DFS * DMODEL / 4);
    k_round<<<2048, 256>>>(shd, wr_base + SHD_OFF,  DMODEL * DFS / 4);
    k_gemm_gateup<<<dim3(32, 16, 1), 128, SMEM_DYN>>>();
    k_swiglu1<<<(TTOK * DFS / 4) / 256, 256>>>();
    k_gemm_down<<<dim3(8, 16, 1), 128, SMEM_DYN>>>();
    k_gemm_expert_gu<<<dim3(8, 16, NEXP), 128, SMEM_DYN>>>(gq, uq, gs, us);
    k_swiglu2<<<dim3(MAXPE, NEXP, 1), 128>>>();
    k_gemm_expert_down<<<dim3(8, 16, NEXP), 128, SMEM_DYN>>>(dq, ds);
    k_combine<<<TTOK, 256>>>(out);
}

// round 8
// speedup vs baseline: 3.6109x; 1.7995x over previous
#include <cuda_runtime.h>
#include <cuda_fp16.h>
#include <cstdint>

#define TTOK   2048
#define DMODEL 1024
#define DFS    2048
#define DFE    512
#define NEXP   8
#define MAXPE  2048

typedef unsigned long long u64;

// ---------------- scratch (device globals; no allocation allowed) ----------
__device__ __half g_xh   [TTOK * DMODEL];            // fp16 x
__device__ __half g_wgu  [2 * DFS * DMODEL];         // interleaved gate/up shared weights
__device__ __half g_wdh  [DMODEL * DFS];             // shared down weights
__device__ __half g_egu  [NEXP * 2 * DFE * DMODEL];  // interleaved expert gate/up (fp16)
__device__ __half g_edh  [NEXP * DMODEL * DFE];      // expert down (fp16)
__device__ __half g_act1h[TTOK * DFS];               // shared swiglu out (fp16)
__device__ __half g_act2h[NEXP * MAXPE * DFE];       // expert swiglu out (fp16)
__device__ float  g_sgu  [NEXP * 2 * DFE];           // interleaved gate_s/up_s
__device__ float  g_sh   [TTOK * DMODEL];            // shared MLP out (f32)
__device__ float  g_eo   [NEXP * MAXPE * DMODEL];    // expert out (f32)
__device__ int    g_cnt  [NEXP];
__device__ int    g_tok  [NEXP * MAXPE];
__device__ int    g_slot0[TTOK];
__device__ int    g_slot1[TTOK];
__device__ float  g_c0[TTOK];
__device__ float  g_c1[TTOK];
__device__ float  g_cs[TTOK];

// ---------------- PTX helpers ----------------------------------------------
__device__ __forceinline__ void cp16(uint32_t dst, const void* src) {
    asm volatile("cp.async.cg.shared.global [%0], [%1], 16;" :: "r"(dst), "l"(src));
}
__device__ __forceinline__ void cp_commit() {
    asm volatile("cp.async.commit_group;" ::: "memory");
}
__device__ __forceinline__ void cp_wait2() {
    asm volatile("cp.async.wait_group 2;" ::: "memory");
}
#define LDSM4(R, addr) \
    asm volatile("ldmatrix.sync.aligned.m8n8.x4.shared.b16 {%0,%1,%2,%3}, [%4];" \
                 : "=r"((R)[0]), "=r"((R)[1]), "=r"((R)[2]), "=r"((R)[3]) \
                 : "r"(addr))
__device__ __forceinline__ void mma_h(float* c, const uint32_t* a,
                                      uint32_t b0, uint32_t b1) {
    asm volatile(
        "mma.sync.aligned.m16n8k16.row.col.f32.f16.f16.f32 "
        "{%0,%1,%2,%3}, {%4,%5,%6,%7}, {%8,%9}, {%0,%1,%2,%3};"
        : "+f"(c[0]), "+f"(c[1]), "+f"(c[2]), "+f"(c[3])
        : "r"(a[0]), "r"(a[1]), "r"(a[2]), "r"(a[3]), "r"(b0), "r"(b1));
}

#define STAGE_BYTES 16384       // A 8KB + B 8KB per stage (BK=32 fp16)
#define SMEM_DYN    65536       // 4 stages

// ---------------- fp16 mma GEMM ---------------------------------------------
// C[m,n] = sum_k A[m,k]*B[n,k]; 128x128 tile, BK=32, 128 threads, 4-stage pipe.
// EPI: 0 = f32 out, 1 = f32 out * scale[col], 2 = swiglu->fp16, 3 = swiglu*scale->fp16
template<bool GATHER, int EPI>
__device__ __forceinline__ void gemm_h(
    const __half* __restrict__ A, const int* __restrict__ list,
    int Mcnt, int K,
    const __half* __restrict__ B,
    const float* __restrict__ scale,
    void* __restrict__ Cout, int ldc, int m0)
{
    extern __shared__ char smc[];
    const uint32_t smb = (uint32_t)__cvta_generic_to_shared(smc);
    const int tid  = threadIdx.x;
    const int wid  = tid >> 5;
    const int lane = tid & 31;
    const int g    = lane >> 2;
    const int t    = lane & 3;
    const int warpM = (wid & 1) * 64;
    const int warpN = (wid >> 1) * 64;

    // staging source rows (row = tid)
    int ar = m0 + tid;
    if (ar >= Mcnt) ar = Mcnt - 1;
    const char* arow = (const char*)(A + (size_t)(GATHER ? list[ar] : ar) * K);
    const char* brow = (const char*)(B + (size_t)tid * K);

    const uint32_t swz  = (tid >> 1) & 3;
    const uint32_t aDst = smb + tid * 64;
    const uint32_t bDst = smb + 8192 + tid * 64;

    // ldmatrix per-lane offsets
    const int q  = lane >> 3;
    const int rr = lane & 7;
    const int arow0 = warpM + (q & 1) * 8 + rr;
    const int brow0 = warpN + (q >> 1) * 8 + rr;
    const uint32_t aswz = (arow0 >> 1) & 3;
    const uint32_t bswz = (brow0 >> 1) & 3;
    uint32_t aoffj[2], boffj[2];
    aoffj[0] = arow0 * 64 + ((((uint32_t)(q >> 1))     ^ aswz) * 16);
    aoffj[1] = arow0 * 64 + (((2u + (uint32_t)(q >> 1)) ^ aswz) * 16);
    boffj[0] = brow0 * 64 + ((((uint32_t)(q & 1))      ^ bswz) * 16);
    boffj[1] = brow0 * 64 + (((2u + (uint32_t)(q & 1))  ^ bswz) * 16);

    float acc[4][8][4];
#pragma unroll
    for (int m = 0; m < 4; m++)
#pragma unroll
        for (int n = 0; n < 8; n++)
#pragma unroll
            for (int z = 0; z < 4; z++) acc[m][n][z] = 0.f;

    const int nch = K >> 5;

    // prologue: stage chunks 0..2
#pragma unroll
    for (int p = 0; p < 3; p++) {
        if (p < nch) {
            const uint32_t sb = p * STAGE_BYTES;
            const int kb = p * 64;   // bytes along K (32 halves)
#pragma unroll
            for (int c = 0; c < 4; c++) {
                cp16(aDst + sb + (((uint32_t)c ^ swz) * 16), arow + kb + c * 16);
                cp16(bDst + sb + (((uint32_t)c ^ swz) * 16), brow + kb + c * 16);
            }
        }
        cp_commit();
    }

    for (int ch = 0; ch < nch; ch++) {
        cp_wait2();
        __syncthreads();
        // stage chunk ch+3
        if (ch + 3 < nch) {
            const uint32_t sb = ((ch + 3) & 3) * STAGE_BYTES;
            const int kb = (ch + 3) * 64;
#pragma unroll
            for (int c = 0; c < 4; c++) {
                cp16(aDst + sb + (((uint32_t)c ^ swz) * 16), arow + kb + c * 16);
                cp16(bDst + sb + (((uint32_t)c ^ swz) * 16), brow + kb + c * 16);
            }
        }
        cp_commit();
        // compute chunk ch
        const uint32_t ab = smb + (ch & 3) * STAGE_BYTES;
        const uint32_t bb = ab + 8192;
#pragma unroll
        for (int j = 0; j < 2; j++) {
            uint32_t aF[4][4], bF[4][4];
#pragma unroll
            for (int mt = 0; mt < 4; mt++) LDSM4(aF[mt], ab + aoffj[j] + mt * 1024);
#pragma unroll
            for (int np = 0; np < 4; np++) LDSM4(bF[np], bb + boffj[j] + np * 1024);
#pragma unroll
            for (int mt = 0; mt < 4; mt++)
#pragma unroll
                for (int n = 0; n < 8; n++)
                    mma_h(acc[mt][n], aF[mt],
                          bF[n >> 1][(n & 1) * 2], bF[n >> 1][(n & 1) * 2 + 1]);
        }
    }

    // ---- epilogue
    if (EPI <= 1) {
        float* Cf = (float*)Cout;
#pragma unroll
        for (int n = 0; n < 8; n++) {
            const int col = warpN + n * 8 + 2 * t;
            float s0 = 1.f, s1 = 1.f;
            if (EPI == 1) {
                float2 sp = *(const float2*)(scale + col);
                s0 = sp.x; s1 = sp.y;
            }
#pragma unroll
            for (int mt = 0; mt < 4; mt++) {
                int r = m0 + warpM + mt * 16 + g;
                if (r < Mcnt)
                    *(float2*)(Cf + (size_t)r * ldc + col) =
                        make_float2(acc[mt][n][0] * s0, acc[mt][n][1] * s1);
                if (r + 8 < Mcnt)
                    *(float2*)(Cf + (size_t)(r + 8) * ldc + col) =
                        make_float2(acc[mt][n][2] * s0, acc[mt][n][3] * s1);
            }
        }
    } else {
        __half* Ch = (__half*)Cout;
#pragma unroll
        for (int n = 0; n < 8; n++) {
            const int colB = warpN + n * 8 + 2 * t;   // even col = gate, odd = up
            float sg = 1.f, su = 1.f;
            if (EPI == 3) {
                float2 sp = *(const float2*)(scale + colB);
                sg = sp.x; su = sp.y;
            }
            const int oc = colB >> 1;
#pragma unroll
            for (int mt = 0; mt < 4; mt++) {
                int r = m0 + warpM + mt * 16 + g;
                if (r < Mcnt) {
                    float gg = acc[mt][n][0] * sg, uu = acc[mt][n][1] * su;
                    Ch[(size_t)r * ldc + oc] =
                        __float2half_rn(gg * uu / (1.f + __expf(-gg)));
                }
                if (r + 8 < Mcnt) {
                    float gg = acc[mt][n][2] * sg, uu = acc[mt][n][3] * su;
                    Ch[(size_t)(r + 8) * ldc + oc] =
                        __float2half_rn(gg * uu / (1.f + __expf(-gg)));
                }
            }
        }
    }
}

// ---------------- GEMM kernel wrappers --------------------------------------
__global__ __launch_bounds__(128, 2)
void k_gemm_gateup() {        // x @ interleaved(gate|up)^T -> swiglu -> act1h
    int n0 = blockIdx.x * 128;
    int m0 = blockIdx.y * 128;
    gemm_h<false, 2>(g_xh, 0, TTOK, DMODEL,
                     g_wgu + (size_t)n0 * DMODEL, 0,
                     g_act1h + (n0 >> 1), DFS, m0);
}

__global__ __launch_bounds__(128, 2)
void k_gemm_down() {          // act1h @ shd^T -> g_sh (f32)
    int n0 = blockIdx.x * 128;
    int m0 = blockIdx.y * 128;
    gemm_h<false, 0>(g_act1h, 0, TTOK, DFS,
                     g_wdh + (size_t)n0 * DFS, 0,
                     g_sh + n0, DMODEL, m0);
}

__global__ __launch_bounds__(128, 2)
void k_gemm_egu() {           // gathered x @ expert interleaved gu -> swiglu*scale -> act2h
    int e = blockIdx.z;
    int cnt = g_cnt[e];
    int m0 = blockIdx.y * 128;
    if (m0 >= cnt) return;
    int n0 = blockIdx.x * 128;
    gemm_h<true, 3>(g_xh, g_tok + e * MAXPE, cnt, DMODEL,
                    g_egu + ((size_t)e * 2 * DFE + n0) * DMODEL,
                    g_sgu + e * 2 * DFE + n0,
                    g_act2h + (size_t)e * MAXPE * DFE + (n0 >> 1), DFE, m0);
}

__global__ __launch_bounds__(128, 2)
void k_gemm_edown(const float* __restrict__ ds) {  // act2h @ expert down * scale -> g_eo
    int e = blockIdx.z;
    int cnt = g_cnt[e];
    int m0 = blockIdx.y * 128;
    if (m0 >= cnt) return;
    int n0 = blockIdx.x * 128;
    gemm_h<false, 1>(g_act2h + (size_t)e * MAXPE * DFE, 0, cnt, DFE,
                     g_edh + ((size_t)e * DMODEL + n0) * DFE,
                     ds + e * DMODEL + n0,
                     g_eo + (size_t)e * MAXPE * DMODEL + n0, DMODEL, m0);
}

// ---------------- conversion kernels ----------------------------------------
__global__ void k_f2h(const float* __restrict__ s, __half* __restrict__ d, int n4) {
    int i = blockIdx.x * blockDim.x + threadIdx.x;
    if (i >= n4) return;
    float4 v = ((const float4*)s)[i];
    ((__half2*)d)[2 * i]     = __floats2half2_rn(v.x, v.y);
    ((__half2*)d)[2 * i + 1] = __floats2half2_rn(v.z, v.w);
}

// interleave rows: src row r (grouped by rpg) -> dst row grp*2*rpg + 2*(r%rpg) + off
__global__ void k_f2h_ilv(const float* __restrict__ s, __half* __restrict__ d,
                          int total4, int rowlen4, int rpg, int off) {
    int i = blockIdx.x * blockDim.x + threadIdx.x;
    if (i >= total4) return;
    int r = i / rowlen4, c = i % rowlen4;
    int dr = (r / rpg) * 2 * rpg + 2 * (r % rpg) + off;
    float4 v = ((const float4*)s)[i];
    size_t o = (size_t)dr * rowlen4 * 2 + c * 2;
    ((__half2*)d)[o]     = __floats2half2_rn(v.x, v.y);
    ((__half2*)d)[o + 1] = __floats2half2_rn(v.z, v.w);
}

__global__ void k_i2h(const int* __restrict__ s, __half* __restrict__ d, int n4) {
    int i = blockIdx.x * blockDim.x + threadIdx.x;
    if (i >= n4) return;
    int4 v = ((const int4*)s)[i];
    ((__half2*)d)[2 * i]     = __floats2half2_rn((float)v.x, (float)v.y);
    ((__half2*)d)[2 * i + 1] = __floats2half2_rn((float)v.z, (float)v.w);
}

__global__ void k_i2h_ilv(const int* __restrict__ s, __half* __restrict__ d,
                          int total4, int rowlen4, int rpg, int off) {
    int i = blockIdx.x * blockDim.x + threadIdx.x;
    if (i >= total4) return;
    int r = i / rowlen4, c = i % rowlen4;
    int dr = (r / rpg) * 2 * rpg + 2 * (r % rpg) + off;
    int4 v = ((const int4*)s)[i];
    size_t o = (size_t)dr * rowlen4 * 2 + c * 2;
    ((__half2*)d)[o]     = __floats2half2_rn((float)v.x, (float)v.y);
    ((__half2*)d)[o + 1] = __floats2half2_rn((float)v.z, (float)v.w);
}

__global__ void k_ilv_scales(const float* __restrict__ gs, const float* __restrict__ us) {
    int i = blockIdx.x * blockDim.x + threadIdx.x;
    if (i >= NEXP * DFE) return;
    int e = i / DFE, f = i % DFE;
    g_sgu[e * 2 * DFE + 2 * f]     = gs[i];
    g_sgu[e * 2 * DFE + 2 * f + 1] = us[i];
}

// ---------------- small kernels ---------------------------------------------
__global__ void k_zero() {
    if (threadIdx.x < NEXP) g_cnt[threadIdx.x] = 0;
}

__global__ void k_router(const float* __restrict__ x,
                         const float* __restrict__ rw,
                         const float* __restrict__ alpha) {
    int warp = (blockIdx.x * blockDim.x + threadIdx.x) >> 5;
    int lane = threadIdx.x & 31;
    if (warp >= TTOK) return;
    const float* xr = x + (size_t)warp * DMODEL;
    float acc[NEXP];
#pragma unroll
    for (int e = 0; e < NEXP; e++) acc[e] = 0.f;
    for (int d = lane; d < DMODEL; d += 32) {
        float xv = xr[d];
#pragma unroll
        for (int e = 0; e < NEXP; e++) acc[e] += xv * rw[e * DMODEL + d];
    }
#pragma unroll
    for (int e = 0; e < NEXP; e++)
#pragma unroll
        for (int off = 16; off; off >>= 1)
            acc[e] += __shfl_xor_sync(0xffffffffu, acc[e], off);
    if (lane == 0) {
        int e0 = 0; float v0 = acc[0];
#pragma unroll
        for (int e = 1; e < NEXP; e++) if (acc[e] > v0) { v0 = acc[e]; e0 = e; }
        int e1 = -1; float v1 = -3.4e38f;
#pragma unroll
        for (int e = 0; e < NEXP; e++) if (e != e0 && acc[e] > v1) { v1 = acc[e]; e1 = e; }
        float w0 = 1.f / (1.f + __expf(v1 - v0));
        float w1 = 1.f - w0;
        float c0 = w0 * alpha[e0];
        float c1 = w1 * alpha[e1];
        int p0 = atomicAdd(&g_cnt[e0], 1);
        int p1 = atomicAdd(&g_cnt[e1], 1);
        g_tok[e0 * MAXPE + p0] = warp;
        g_tok[e1 * MAXPE + p1] = warp;
        g_slot0[warp] = e0 * MAXPE + p0;
        g_slot1[warp] = e1 * MAXPE + p1;
        g_c0[warp] = c0;
        g_c1[warp] = c1;
        g_cs[warp] = 1.f - c0 - c1;
    }
}

__global__ void k_combine(float* __restrict__ out) {
    int tok = blockIdx.x;
    int c = threadIdx.x;
    float cs = g_cs[tok], c0 = g_c0[tok], c1 = g_c1[tok];
    size_t s0 = (size_t)g_slot0[tok] * DMODEL;
    size_t s1 = (size_t)g_slot1[tok] * DMODEL;
    float4 sh = *(const float4*)&g_sh[(size_t)tok * DMODEL + c * 4];
    float4 a  = *(const float4*)&g_eo[s0 + c * 4];
    float4 b  = *(const float4*)&g_eo[s1 + c * 4];
    float4 o;
    o.x = cs * sh.x + c0 * a.x + c1 * b.x;
    o.y = cs * sh.y + c0 * a.y + c1 * b.y;
    o.z = cs * sh.z + c0 * a.z + c1 * b.z;
    o.w = cs * sh.w + c0 * a.w + c1 * b.w;
    *(float4*)&out[(size_t)tok * DMODEL + c * 4] = o;
}

// ---------------- launch ----------------------------------------------------
extern "C" void kernel_launch(void* const* d_in, const int* in_sizes, int n_in,
                              void* d_out, int out_size) {
    const float *x, *rw, *shg, *shu, *shd, *gs, *us, *ds, *al;
    const int *gq, *uq, *dq;
    if (in_sizes[0] == NEXP) {
        al  = (const float*)d_in[0];
        dq  = (const int*)  d_in[1];
        ds  = (const float*)d_in[2];
        gq  = (const int*)  d_in[3];
        gs  = (const float*)d_in[4];
        rw  = (const float*)d_in[5];
        shd = (const float*)d_in[6];
        shg = (const float*)d_in[7];
        shu = (const float*)d_in[8];
        uq  = (const int*)  d_in[10];
        us  = (const float*)d_in[11];
        x   = (const float*)d_in[12];
    } else {
        x   = (const float*)d_in[0];
        rw  = (const float*)d_in[1];
        shg = (const float*)d_in[2];
        shu = (const float*)d_in[3];
        shd = (const float*)d_in[4];
        gs  = (const float*)d_in[5];
        us  = (const float*)d_in[6];
        ds  = (const float*)d_in[7];
        al  = (const float*)d_in[8];
        gq  = (const int*)  d_in[9];
        uq  = (const int*)  d_in[10];
        dq  = (const int*)  d_in[11];
    }
    float* out = (float*)d_out;

    static int attr_done = 0;
    if (!attr_done) {
        cudaFuncSetAttribute(k_gemm_gateup, cudaFuncAttributeMaxDynamicSharedMemorySize, SMEM_DYN);
        cudaFuncSetAttribute(k_gemm_down,   cudaFuncAttributeMaxDynamicSharedMemorySize, SMEM_DYN);
        cudaFuncSetAttribute(k_gemm_egu,    cudaFuncAttributeMaxDynamicSharedMemorySize, SMEM_DYN);
        cudaFuncSetAttribute(k_gemm_edown,  cudaFuncAttributeMaxDynamicSharedMemorySize, SMEM_DYN);
        attr_done = 1;
    }

    __half* xh;   cudaGetSymbolAddress((void**)&xh,  g_xh);
    __half* wgu;  cudaGetSymbolAddress((void**)&wgu, g_wgu);
    __half* wdh;  cudaGetSymbolAddress((void**)&wdh, g_wdh);
    __half* egu;  cudaGetSymbolAddress((void**)&egu, g_egu);
    __half* edh;  cudaGetSymbolAddress((void**)&edh, g_edh);

    k_zero<<<1, 32>>>();
    k_router<<<TTOK / 8, 256>>>(x, rw, al);

    // fp16 conversions
    const int D4 = DMODEL / 4;
    k_f2h<<<(TTOK * D4 + 255) / 256, 256>>>(x, xh, TTOK * D4);
    k_f2h_ilv<<<(DFS * D4 + 255) / 256, 256>>>(shg, wgu, DFS * D4, D4, DFS, 0);
    k_f2h_ilv<<<(DFS * D4 + 255) / 256, 256>>>(shu, wgu, DFS * D4, D4, DFS, 1);
    k_f2h<<<(DMODEL * DFS / 4 + 255) / 256, 256>>>(shd, wdh, DMODEL * DFS / 4);
    k_i2h_ilv<<<(NEXP * DFE * D4 + 255) / 256, 256>>>(gq, egu, NEXP * DFE * D4, D4, DFE, 0);
    k_i2h_ilv<<<(NEXP * DFE * D4 + 255) / 256, 256>>>(uq, egu, NEXP * DFE * D4, D4, DFE, 1);
    k_i2h<<<(NEXP * DMODEL * DFE / 4 + 255) / 256, 256>>>(dq, edh, NEXP * DMODEL * DFE / 4);
    k_ilv_scales<<<(NEXP * DFE + 255) / 256, 256>>>(gs, us);

    // GEMMs (swiglu fused into gateup/egu epilogues)
    k_gemm_gateup<<<dim3(32, 16, 1), 128, SMEM_DYN>>>();
    k_gemm_down<<<dim3(8, 16, 1), 128, SMEM_DYN>>>();
    k_gemm_egu<<<dim3(8, 16, NEXP), 128, SMEM_DYN>>>();
    k_gemm_edown<<<dim3(8, 16, NEXP), 128, SMEM_DYN>>>(ds);

    k_combine<<<TTOK, 256>>>(out);
}

// round 10
// speedup vs baseline: 4.8469x; 1.3423x over previous
#include <cuda_runtime.h>
#include <cuda_fp16.h>
#include <cstdint>

#define TTOK   2048
#define DMODEL 1024
#define DFS    2048
#define DFE    512
#define NEXP   8
#define MAXPE  2048

typedef unsigned long long u64;

// ---------------- scratch (device globals; no allocation allowed) ----------
__device__ __half g_xh   [TTOK * DMODEL];            // fp16 x
__device__ __half g_wgu  [2 * DFS * DMODEL];         // interleaved gate/up shared weights
__device__ __half g_wdh  [DMODEL * DFS];             // shared down weights
__device__ __half g_egu  [NEXP * 2 * DFE * DMODEL];  // interleaved expert gate/up (fp16)
__device__ __half g_edh  [NEXP * DMODEL * DFE];      // expert down (fp16)
__device__ __half g_act1h[TTOK * DFS];               // shared swiglu out (fp16)
__device__ __half g_act2h[NEXP * MAXPE * DFE];       // expert swiglu out (fp16)
__device__ float  g_sgu  [NEXP * 2 * DFE];           // interleaved gate_s/up_s
__device__ float  g_sh   [TTOK * DMODEL];            // shared MLP out (f32)
__device__ float  g_eo   [NEXP * MAXPE * DMODEL];    // expert out (f32)
__device__ int    g_cnt  [NEXP];
__device__ int    g_tok  [NEXP * MAXPE];
__device__ int    g_slot0[TTOK];
__device__ int    g_slot1[TTOK];
__device__ float  g_c0[TTOK];
__device__ float  g_c1[TTOK];
__device__ float  g_cs[TTOK];

// ---------------- PTX helpers ----------------------------------------------
__device__ __forceinline__ void cp16(uint32_t dst, const void* src) {
    asm volatile("cp.async.cg.shared.global [%0], [%1], 16;" :: "r"(dst), "l"(src));
}
__device__ __forceinline__ void cp_commit() {
    asm volatile("cp.async.commit_group;" ::: "memory");
}
__device__ __forceinline__ void cp_wait2() {
    asm volatile("cp.async.wait_group 2;" ::: "memory");
}
#define LDSM4(R, addr) \
    asm volatile("ldmatrix.sync.aligned.m8n8.x4.shared.b16 {%0,%1,%2,%3}, [%4];" \
                 : "=r"((R)[0]), "=r"((R)[1]), "=r"((R)[2]), "=r"((R)[3]) \
                 : "r"(addr))
__device__ __forceinline__ void mma_h(float* c, const uint32_t* a,
                                      uint32_t b0, uint32_t b1) {
    asm volatile(
        "mma.sync.aligned.m16n8k16.row.col.f32.f16.f16.f32 "
        "{%0,%1,%2,%3}, {%4,%5,%6,%7}, {%8,%9}, {%0,%1,%2,%3};"
        : "+f"(c[0]), "+f"(c[1]), "+f"(c[2]), "+f"(c[3])
        : "r"(a[0]), "r"(a[1]), "r"(a[2]), "r"(a[3]), "r"(b0), "r"(b1));
}

#define STAGE_BYTES 16384       // A 8KB + B 8KB per stage (BK=32 fp16)
#define SMEM_DYN    65536       // 4 stages

// ---------------- fp16 mma GEMM ---------------------------------------------
// C[m,n] = sum_k A[m,k]*B[n,k]; 128x128 tile, BK=32, 256 threads (8 warps,
// warp tile 32x64), 4-stage cp.async pipe, 2 CTAs/SM.
// EPI: 0 = f32 out, 1 = f32 out * scale[col], 2 = swiglu->fp16, 3 = swiglu*scale->fp16
template<bool GATHER, int EPI>
__device__ __forceinline__ void gemm_h(
    const __half* __restrict__ A, const int* __restrict__ list,
    int Mcnt, int K,
    const __half* __restrict__ B,
    const float* __restrict__ scale,
    void* __restrict__ Cout, int ldc, int m0)
{
    extern __shared__ char smc[];
    const uint32_t smb = (uint32_t)__cvta_generic_to_shared(smc);
    const int tid  = threadIdx.x;
    const int wid  = tid >> 5;
    const int lane = tid & 31;
    const int g    = lane >> 2;
    const int t    = lane & 3;
    const int warpM = (wid & 3) * 32;
    const int warpN = (wid >> 2) * 64;

    // staging: thread covers half of row (tid>>1), bytes [(tid&1)*32, +32)
    const int srow = tid >> 1;
    const int sh2  = tid & 1;
    int ar = m0 + srow;
    if (ar >= Mcnt) ar = Mcnt - 1;
    const char* arow = (const char*)(A + (size_t)(GATHER ? list[ar] : ar) * K);
    const char* brow = (const char*)(B + (size_t)srow * K);
    const uint32_t sswz = (srow >> 1) & 3;
    const uint32_t aDst = smb + srow * 64;
    const uint32_t bDst = smb + 8192 + srow * 64;
    const uint32_t sl0 = (uint32_t)(sh2 * 2);
    const uint32_t sl1 = sl0 + 1;

    // ldmatrix per-lane offsets
    const int q  = lane >> 3;
    const int rr = lane & 7;
    const int arow0 = warpM + (q & 1) * 8 + rr;
    const int brow0 = warpN + (q >> 1) * 8 + rr;
    const uint32_t aswz = (arow0 >> 1) & 3;
    const uint32_t bswz = (brow0 >> 1) & 3;
    uint32_t aoffj[2], boffj[2];
    aoffj[0] = arow0 * 64 + ((((uint32_t)(q >> 1))      ^ aswz) * 16);
    aoffj[1] = arow0 * 64 + (((2u + (uint32_t)(q >> 1)) ^ aswz) * 16);
    boffj[0] = brow0 * 64 + ((((uint32_t)(q & 1))       ^ bswz) * 16);
    boffj[1] = brow0 * 64 + (((2u + (uint32_t)(q & 1))  ^ bswz) * 16);

    float acc[2][8][4];
#pragma unroll
    for (int m = 0; m < 2; m++)
#pragma unroll
        for (int n = 0; n < 8; n++)
#pragma unroll
            for (int z = 0; z < 4; z++) acc[m][n][z] = 0.f;

    const int nch = K >> 5;

    // prologue: stage chunks 0..2
#pragma unroll
    for (int p = 0; p < 3; p++) {
        if (p < nch) {
            const uint32_t sb = p * STAGE_BYTES;
            const int kb = p * 64;
            cp16(aDst + sb + ((sl0 ^ sswz) * 16), arow + kb + sl0 * 16);
            cp16(aDst + sb + ((sl1 ^ sswz) * 16), arow + kb + sl1 * 16);
            cp16(bDst + sb + ((sl0 ^ sswz) * 16), brow + kb + sl0 * 16);
            cp16(bDst + sb + ((sl1 ^ sswz) * 16), brow + kb + sl1 * 16);
        }
        cp_commit();
    }

    for (int ch = 0; ch < nch; ch++) {
        cp_wait2();
        __syncthreads();
        if (ch + 3 < nch) {
            const uint32_t sb = ((ch + 3) & 3) * STAGE_BYTES;
            const int kb = (ch + 3) * 64;
            cp16(aDst + sb + ((sl0 ^ sswz) * 16), arow + kb + sl0 * 16);
            cp16(aDst + sb + ((sl1 ^ sswz) * 16), arow + kb + sl1 * 16);
            cp16(bDst + sb + ((sl0 ^ sswz) * 16), brow + kb + sl0 * 16);
            cp16(bDst + sb + ((sl1 ^ sswz) * 16), brow + kb + sl1 * 16);
        }
        cp_commit();
        const uint32_t ab = smb + (ch & 3) * STAGE_BYTES;
        const uint32_t bb = ab + 8192;
#pragma unroll
        for (int j = 0; j < 2; j++) {
            uint32_t aF[2][4], bF[4][4];
#pragma unroll
            for (int mt = 0; mt < 2; mt++) LDSM4(aF[mt], ab + aoffj[j] + mt * 1024);
#pragma unroll
            for (int np = 0; np < 4; np++) LDSM4(bF[np], bb + boffj[j] + np * 1024);
#pragma unroll
            for (int mt = 0; mt < 2; mt++)
#pragma unroll
                for (int n = 0; n < 8; n++)
                    mma_h(acc[mt][n], aF[mt],
                          bF[n >> 1][(n & 1) * 2], bF[n >> 1][(n & 1) * 2 + 1]);
        }
    }

    // ---- epilogue
    if (EPI <= 1) {
        float* Cf = (float*)Cout;
#pragma unroll
        for (int n = 0; n < 8; n++) {
            const int col = warpN + n * 8 + 2 * t;
            float s0 = 1.f, s1 = 1.f;
            if (EPI == 1) {
                float2 sp = *(const float2*)(scale + col);
                s0 = sp.x; s1 = sp.y;
            }
#pragma unroll
            for (int mt = 0; mt < 2; mt++) {
                int r = m0 + warpM + mt * 16 + g;
                if (r < Mcnt)
                    *(float2*)(Cf + (size_t)r * ldc + col) =
                        make_float2(acc[mt][n][0] * s0, acc[mt][n][1] * s1);
                if (r + 8 < Mcnt)
                    *(float2*)(Cf + (size_t)(r + 8) * ldc + col) =
                        make_float2(acc[mt][n][2] * s0, acc[mt][n][3] * s1);
            }
        }
    } else {
        __half* Ch = (__half*)Cout;
#pragma unroll
        for (int n = 0; n < 8; n++) {
            const int colB = warpN + n * 8 + 2 * t;   // even col = gate, odd = up
            float sg = 1.f, su = 1.f;
            if (EPI == 3) {
                float2 sp = *(const float2*)(scale + colB);
                sg = sp.x; su = sp.y;
            }
            const int oc = colB >> 1;
#pragma unroll
            for (int mt = 0; mt < 2; mt++) {
                int r = m0 + warpM + mt * 16 + g;
                if (r < Mcnt) {
                    float gg = acc[mt][n][0] * sg, uu = acc[mt][n][1] * su;
                    Ch[(size_t)r * ldc + oc] =
                        __float2half_rn(gg * uu / (1.f + __expf(-gg)));
                }
                if (r + 8 < Mcnt) {
                    float gg = acc[mt][n][2] * sg, uu = acc[mt][n][3] * su;
                    Ch[(size_t)(r + 8) * ldc + oc] =
                        __float2half_rn(gg * uu / (1.f + __expf(-gg)));
                }
            }
        }
    }
}

// ---------------- GEMM kernel wrappers --------------------------------------
__global__ __launch_bounds__(256, 2)
void k_gemm_gateup() {        // x @ interleaved(gate|up)^T -> swiglu -> act1h
    int n0 = blockIdx.x * 128;
    int m0 = blockIdx.y * 128;
    gemm_h<false, 2>(g_xh, 0, TTOK, DMODEL,
                     g_wgu + (size_t)n0 * DMODEL, 0,
                     g_act1h + (n0 >> 1), DFS, m0);
}

__global__ __launch_bounds__(256, 2)
void k_gemm_down() {          // act1h @ shd^T -> g_sh (f32)
    int n0 = blockIdx.x * 128;
    int m0 = blockIdx.y * 128;
    gemm_h<false, 0>(g_act1h, 0, TTOK, DFS,
                     g_wdh + (size_t)n0 * DFS, 0,
                     g_sh + n0, DMODEL, m0);
}

__global__ __launch_bounds__(256, 2)
void k_gemm_egu() {           // gathered x @ expert interleaved gu -> swiglu*scale -> act2h
    int e = blockIdx.z;
    int cnt = g_cnt[e];
    int m0 = blockIdx.y * 128;
    if (m0 >= cnt) return;
    int n0 = blockIdx.x * 128;
    gemm_h<true, 3>(g_xh, g_tok + e * MAXPE, cnt, DMODEL,
                    g_egu + ((size_t)e * 2 * DFE + n0) * DMODEL,
                    g_sgu + e * 2 * DFE + n0,
                    g_act2h + (size_t)e * MAXPE * DFE + (n0 >> 1), DFE, m0);
}

__global__ __launch_bounds__(256, 2)
void k_gemm_edown(const float* __restrict__ ds) {  // act2h @ expert down * scale -> g_eo
    int e = blockIdx.z;
    int cnt = g_cnt[e];
    int m0 = blockIdx.y * 128;
    if (m0 >= cnt) return;
    int n0 = blockIdx.x * 128;
    gemm_h<false, 1>(g_act2h + (size_t)e * MAXPE * DFE, 0, cnt, DFE,
                     g_edh + ((size_t)e * DMODEL + n0) * DFE,
                     ds + e * DMODEL + n0,
                     g_eo + (size_t)e * MAXPE * DMODEL + n0, DMODEL, m0);
}

// ---------------- conversion kernels (MLP=4) --------------------------------
__global__ void k_f2h(const float* __restrict__ s, __half* __restrict__ d, int n4) {
    int i0 = blockIdx.x * (blockDim.x * 4) + threadIdx.x;
#pragma unroll
    for (int u = 0; u < 4; u++) {
        int i = i0 + u * blockDim.x;
        if (i < n4) {
            float4 v = ((const float4*)s)[i];
            ((__half2*)d)[2 * i]     = __floats2half2_rn(v.x, v.y);
            ((__half2*)d)[2 * i + 1] = __floats2half2_rn(v.z, v.w);
        }
    }
}

// interleave rows: src row r (grouped by rpg) -> dst row grp*2*rpg + 2*(r%rpg) + off
__global__ void k_f2h_ilv(const float* __restrict__ s, __half* __restrict__ d,
                          int total4, int rowlen4, int rpg, int off) {
    int i0 = blockIdx.x * (blockDim.x * 4) + threadIdx.x;
#pragma unroll
    for (int u = 0; u < 4; u++) {
        int i = i0 + u * blockDim.x;
        if (i < total4) {
            int r = i / rowlen4, c = i % rowlen4;
            int dr = (r / rpg) * 2 * rpg + 2 * (r % rpg) + off;
            float4 v = ((const float4*)s)[i];
            size_t o = (size_t)dr * rowlen4 * 2 + c * 2;
            ((__half2*)d)[o]     = __floats2half2_rn(v.x, v.y);
            ((__half2*)d)[o + 1] = __floats2half2_rn(v.z, v.w);
        }
    }
}

__global__ void k_i2h(const int* __restrict__ s, __half* __restrict__ d, int n4) {
    int i0 = blockIdx.x * (blockDim.x * 4) + threadIdx.x;
#pragma unroll
    for (int u = 0; u < 4; u++) {
        int i = i0 + u * blockDim.x;
        if (i < n4) {
            int4 v = ((const int4*)s)[i];
            ((__half2*)d)[2 * i]     = __floats2half2_rn((float)v.x, (float)v.y);
            ((__half2*)d)[2 * i + 1] = __floats2half2_rn((float)v.z, (float)v.w);
        }
    }
}

__global__ void k_i2h_ilv(const int* __restrict__ s, __half* __restrict__ d,
                          int total4, int rowlen4, int rpg, int off) {
    int i0 = blockIdx.x * (blockDim.x * 4) + threadIdx.x;
#pragma unroll
    for (int u = 0; u < 4; u++) {
        int i = i0 + u * blockDim.x;
        if (i < total4) {
            int r = i / rowlen4, c = i % rowlen4;
            int dr = (r / rpg) * 2 * rpg + 2 * (r % rpg) + off;
            int4 v = ((const int4*)s)[i];
            size_t o = (size_t)dr * rowlen4 * 2 + c * 2;
            ((__half2*)d)[o]     = __floats2half2_rn((float)v.x, (float)v.y);
            ((__half2*)d)[o + 1] = __floats2half2_rn((float)v.z, (float)v.w);
        }
    }
}

__global__ void k_ilv_scales(const float* __restrict__ gs, const float* __restrict__ us) {
    int i = blockIdx.x * blockDim.x + threadIdx.x;
    if (i >= NEXP * DFE) return;
    int e = i / DFE, f = i % DFE;
    g_sgu[e * 2 * DFE + 2 * f]     = gs[i];
    g_sgu[e * 2 * DFE + 2 * f + 1] = us[i];
}

// ---------------- small kernels ---------------------------------------------
__global__ void k_zero() {
    if (threadIdx.x < NEXP) g_cnt[threadIdx.x] = 0;
}

__global__ void k_router(const float* __restrict__ x,
                         const float* __restrict__ rw,
                         const float* __restrict__ alpha) {
    int warp = (blockIdx.x * blockDim.x + threadIdx.x) >> 5;
    int lane = threadIdx.x & 31;
    if (warp >= TTOK) return;
    const float* xr = x + (size_t)warp * DMODEL;
    float acc[NEXP];
#pragma unroll
    for (int e = 0; e < NEXP; e++) acc[e] = 0.f;
    for (int d = lane; d < DMODEL; d += 32) {
        float xv = xr[d];
#pragma unroll
        for (int e = 0; e < NEXP; e++) acc[e] += xv * rw[e * DMODEL + d];
    }
#pragma unroll
    for (int e = 0; e < NEXP; e++)
#pragma unroll
        for (int off = 16; off; off >>= 1)
            acc[e] += __shfl_xor_sync(0xffffffffu, acc[e], off);
    if (lane == 0) {
        int e0 = 0; float v0 = acc[0];
#pragma unroll
        for (int e = 1; e < NEXP; e++) if (acc[e] > v0) { v0 = acc[e]; e0 = e; }
        int e1 = -1; float v1 = -3.4e38f;
#pragma unroll
        for (int e = 0; e < NEXP; e++) if (e != e0 && acc[e] > v1) { v1 = acc[e]; e1 = e; }
        float w0 = 1.f / (1.f + __expf(v1 - v0));
        float w1 = 1.f - w0;
        float c0 = w0 * alpha[e0];
        float c1 = w1 * alpha[e1];
        int p0 = atomicAdd(&g_cnt[e0], 1);
        int p1 = atomicAdd(&g_cnt[e1], 1);
        g_tok[e0 * MAXPE + p0] = warp;
        g_tok[e1 * MAXPE + p1] = warp;
        g_slot0[warp] = e0 * MAXPE + p0;
        g_slot1[warp] = e1 * MAXPE + p1;
        g_c0[warp] = c0;
        g_c1[warp] = c1;
        g_cs[warp] = 1.f - c0 - c1;
    }
}

__global__ void k_combine(float* __restrict__ out) {
    int tok = blockIdx.x;
    int c = threadIdx.x;
    float cs = g_cs[tok], c0 = g_c0[tok], c1 = g_c1[tok];
    size_t s0 = (size_t)g_slot0[tok] * DMODEL;
    size_t s1 = (size_t)g_slot1[tok] * DMODEL;
    float4 sh = *(const float4*)&g_sh[(size_t)tok * DMODEL + c * 4];
    float4 a  = *(const float4*)&g_eo[s0 + c * 4];
    float4 b  = *(const float4*)&g_eo[s1 + c * 4];
    float4 o;
    o.x = cs * sh.x + c0 * a.x + c1 * b.x;
    o.y = cs * sh.y + c0 * a.y + c1 * b.y;
    o.z = cs * sh.z + c0 * a.z + c1 * b.z;
    o.w = cs * sh.w + c0 * a.w + c1 * b.w;
    *(float4*)&out[(size_t)tok * DMODEL + c * 4] = o;
}

// ---------------- launch ----------------------------------------------------
extern "C" void kernel_launch(void* const* d_in, const int* in_sizes, int n_in,
                              void* d_out, int out_size) {
    const float *x, *rw, *shg, *shu, *shd, *gs, *us, *ds, *al;
    const int *gq, *uq, *dq;
    if (in_sizes[0] == NEXP) {
        al  = (const float*)d_in[0];
        dq  = (const int*)  d_in[1];
        ds  = (const float*)d_in[2];
        gq  = (const int*)  d_in[3];
        gs  = (const float*)d_in[4];
        rw  = (const float*)d_in[5];
        shd = (const float*)d_in[6];
        shg = (const float*)d_in[7];
        shu = (const float*)d_in[8];
        uq  = (const int*)  d_in[10];
        us  = (const float*)d_in[11];
        x   = (const float*)d_in[12];
    } else {
        x   = (const float*)d_in[0];
        rw  = (const float*)d_in[1];
        shg = (const float*)d_in[2];
        shu = (const float*)d_in[3];
        shd = (const float*)d_in[4];
        gs  = (const float*)d_in[5];
        us  = (const float*)d_in[6];
        ds  = (const float*)d_in[7];
        al  = (const float*)d_in[8];
        gq  = (const int*)  d_in[9];
        uq  = (const int*)  d_in[10];
        dq  = (const int*)  d_in[11];
    }
    float* out = (float*)d_out;

    static int attr_done = 0;
    if (!attr_done) {
        cudaFuncSetAttribute(k_gemm_gateup, cudaFuncAttributeMaxDynamicSharedMemorySize, SMEM_DYN);
        cudaFuncSetAttribute(k_gemm_down,   cudaFuncAttributeMaxDynamicSharedMemorySize, SMEM_DYN);
        cudaFuncSetAttribute(k_gemm_egu,    cudaFuncAttributeMaxDynamicSharedMemorySize, SMEM_DYN);
        cudaFuncSetAttribute(k_gemm_edown,  cudaFuncAttributeMaxDynamicSharedMemorySize, SMEM_DYN);
        attr_done = 1;
    }

    __half* xh;   cudaGetSymbolAddress((void**)&xh,  g_xh);
    __half* wgu;  cudaGetSymbolAddress((void**)&wgu, g_wgu);
    __half* wdh;  cudaGetSymbolAddress((void**)&wdh, g_wdh);
    __half* egu;  cudaGetSymbolAddress((void**)&egu, g_egu);
    __half* edh;  cudaGetSymbolAddress((void**)&edh, g_edh);

    k_zero<<<1, 32>>>();
    k_router<<<TTOK / 8, 256>>>(x, rw, al);

    // fp16 conversions (grid = n4 / (256*4))
    const int D4 = DMODEL / 4;
    const int nx4   = TTOK * D4;
    const int ngu4  = DFS * D4;
    const int nd4   = DMODEL * DFS / 4;
    const int negu4 = NEXP * DFE * D4;
    const int ned4  = NEXP * DMODEL * DFE / 4;
    k_f2h<<<(nx4 + 1023) / 1024, 256>>>(x, xh, nx4);
    k_f2h_ilv<<<(ngu4 + 1023) / 1024, 256>>>(shg, wgu, ngu4, D4, DFS, 0);
    k_f2h_ilv<<<(ngu4 + 1023) / 1024, 256>>>(shu, wgu, ngu4, D4, DFS, 1);
    k_f2h<<<(nd4 + 1023) / 1024, 256>>>(shd, wdh, nd4);
    k_i2h_ilv<<<(negu4 + 1023) / 1024, 256>>>(gq, egu, negu4, D4, DFE, 0);
    k_i2h_ilv<<<(negu4 + 1023) / 1024, 256>>>(uq, egu, negu4, D4, DFE, 1);
    k_i2h<<<(ned4 + 1023) / 1024, 256>>>(dq, edh, ned4);
    k_ilv_scales<<<(NEXP * DFE + 255) / 256, 256>>>(gs, us);

    // GEMMs (swiglu fused into gateup/egu epilogues)
    k_gemm_gateup<<<dim3(32, 16, 1), 256, SMEM_DYN>>>();
    k_gemm_down<<<dim3(8, 16, 1), 256, SMEM_DYN>>>();
    k_gemm_egu<<<dim3(8, 16, NEXP), 256, SMEM_DYN>>>();
    k_gemm_edown<<<dim3(8, 16, NEXP), 256, SMEM_DYN>>>(ds);

    k_combine<<<TTOK, 256>>>(out);
}

// round 13
// speedup vs baseline: 5.3410x; 1.1019x over previous
#include <cuda_runtime.h>
#include <cuda_fp16.h>
#include <cstdint>

#define TTOK   2048
#define DMODEL 1024
#define DFS    2048
#define DFE    512
#define NEXP   8
#define MAXPE  2048

typedef unsigned long long u64;

// ---------------- scratch (device globals; no allocation allowed) ----------
__device__ __half g_xh   [TTOK * DMODEL];            // fp16 x
__device__ __half g_wgu  [2 * DFS * DMODEL];         // interleaved gate/up shared weights
__device__ __half g_wdh  [DMODEL * DFS];             // shared down weights
__device__ __half g_egu  [NEXP * 2 * DFE * DMODEL];  // interleaved expert gate/up (fp16)
__device__ __half g_edh  [NEXP * DMODEL * DFE];      // expert down (fp16)
__device__ __half g_act1h[TTOK * DFS];               // shared swiglu out (fp16)
__device__ __half g_act2h[NEXP * MAXPE * DFE];       // expert swiglu out (fp16)
__device__ __half g_shh  [TTOK * DMODEL];            // shared MLP out (fp16)
__device__ __half g_eoh  [NEXP * MAXPE * DMODEL];    // expert out (fp16)
__device__ float  g_sgu  [NEXP * 2 * DFE];           // interleaved gate_s/up_s
__device__ int    g_cnt  [NEXP];
__device__ int    g_tok  [NEXP * MAXPE];
__device__ int    g_slot0[TTOK];
__device__ int    g_slot1[TTOK];
__device__ float  g_c0[TTOK];
__device__ float  g_c1[TTOK];
__device__ float  g_cs[TTOK];

// ---------------- PTX helpers ----------------------------------------------
__device__ __forceinline__ void cp16(uint32_t dst, const void* src) {
    asm volatile("cp.async.cg.shared.global [%0], [%1], 16;" :: "r"(dst), "l"(src));
}
__device__ __forceinline__ void cp_commit() {
    asm volatile("cp.async.commit_group;" ::: "memory");
}
__device__ __forceinline__ void cp_wait2() {
    asm volatile("cp.async.wait_group 2;" ::: "memory");
}
#define LDSM4(R, addr) \
    asm volatile("ldmatrix.sync.aligned.m8n8.x4.shared.b16 {%0,%1,%2,%3}, [%4];" \
                 : "=r"((R)[0]), "=r"((R)[1]), "=r"((R)[2]), "=r"((R)[3]) \
                 : "r"(addr))
__device__ __forceinline__ void mma_h(float* c, const uint32_t* a,
                                      uint32_t b0, uint32_t b1) {
    asm volatile(
        "mma.sync.aligned.m16n8k16.row.col.f32.f16.f16.f32 "
        "{%0,%1,%2,%3}, {%4,%5,%6,%7}, {%8,%9}, {%0,%1,%2,%3};"
        : "+f"(c[0]), "+f"(c[1]), "+f"(c[2]), "+f"(c[3])
        : "r"(a[0]), "r"(a[1]), "r"(a[2]), "r"(a[3]), "r"(b0), "r"(b1));
}

#define STAGE_BYTES 16384       // A 8KB + B 8KB per stage (BK=32 fp16)
#define SMEM_DYN    65536       // 4 stages

// ---------------- fp16 mma GEMM ---------------------------------------------
// C[m,n] = sum_k A[m,k]*B[n,k]; 128x128 tile, BK=32, 256 threads (8 warps,
// warp tile 32x64), 4-stage cp.async pipe, 2 CTAs/SM.
// EPI: 2 = swiglu->fp16, 3 = swiglu*scale->fp16, 4 = ->fp16, 5 = scale->fp16
template<bool GATHER, int EPI>
__device__ __forceinline__ void gemm_h(
    const __half* __restrict__ A, const int* __restrict__ list,
    int Mcnt, int K,
    const __half* __restrict__ B,
    const float* __restrict__ scale,
    __half* __restrict__ Cout, int ldc, int m0)
{
    extern __shared__ char smc[];
    const uint32_t smb = (uint32_t)__cvta_generic_to_shared(smc);
    const int tid  = threadIdx.x;
    const int wid  = tid >> 5;
    const int lane = tid & 31;
    const int g    = lane >> 2;
    const int t    = lane & 3;
    const int warpM = (wid & 3) * 32;
    const int warpN = (wid >> 2) * 64;

    // staging: thread covers half of row (tid>>1), bytes [(tid&1)*32, +32)
    const int srow = tid >> 1;
    const int sh2  = tid & 1;
    int ar = m0 + srow;
    if (ar >= Mcnt) ar = Mcnt - 1;
    const char* arow = (const char*)(A + (size_t)(GATHER ? list[ar] : ar) * K);
    const char* brow = (const char*)(B + (size_t)srow * K);
    const uint32_t sswz = (srow >> 1) & 3;
    const uint32_t aDst = smb + srow * 64;
    const uint32_t bDst = smb + 8192 + srow * 64;
    const uint32_t sl0 = (uint32_t)(sh2 * 2);
    const uint32_t sl1 = sl0 + 1;

    // ldmatrix per-lane offsets
    const int q  = lane >> 3;
    const int rr = lane & 7;
    const int arow0 = warpM + (q & 1) * 8 + rr;
    const int brow0 = warpN + (q >> 1) * 8 + rr;
    const uint32_t aswz = (arow0 >> 1) & 3;
    const uint32_t bswz = (brow0 >> 1) & 3;
    uint32_t aoffj[2], boffj[2];
    aoffj[0] = arow0 * 64 + ((((uint32_t)(q >> 1))      ^ aswz) * 16);
    aoffj[1] = arow0 * 64 + (((2u + (uint32_t)(q >> 1)) ^ aswz) * 16);
    boffj[0] = brow0 * 64 + ((((uint32_t)(q & 1))       ^ bswz) * 16);
    boffj[1] = brow0 * 64 + (((2u + (uint32_t)(q & 1))  ^ bswz) * 16);

    float acc[2][8][4];
#pragma unroll
    for (int m = 0; m < 2; m++)
#pragma unroll
        for (int n = 0; n < 8; n++)
#pragma unroll
            for (int z = 0; z < 4; z++) acc[m][n][z] = 0.f;

    const int nch = K >> 5;

    // prologue: stage chunks 0..2
#pragma unroll
    for (int p = 0; p < 3; p++) {
        if (p < nch) {
            const uint32_t sb = p * STAGE_BYTES;
            const int kb = p * 64;
            cp16(aDst + sb + ((sl0 ^ sswz) * 16), arow + kb + sl0 * 16);
            cp16(aDst + sb + ((sl1 ^ sswz) * 16), arow + kb + sl1 * 16);
            cp16(bDst + sb + ((sl0 ^ sswz) * 16), brow + kb + sl0 * 16);
            cp16(bDst + sb + ((sl1 ^ sswz) * 16), brow + kb + sl1 * 16);
        }
        cp_commit();
    }

    for (int ch = 0; ch < nch; ch++) {
        cp_wait2();
        __syncthreads();
        if (ch + 3 < nch) {
            const uint32_t sb = ((ch + 3) & 3) * STAGE_BYTES;
            const int kb = (ch + 3) * 64;
            cp16(aDst + sb + ((sl0 ^ sswz) * 16), arow + kb + sl0 * 16);
            cp16(aDst + sb + ((sl1 ^ sswz) * 16), arow + kb + sl1 * 16);
            cp16(bDst + sb + ((sl0 ^ sswz) * 16), brow + kb + sl0 * 16);
            cp16(bDst + sb + ((sl1 ^ sswz) * 16), brow + kb + sl1 * 16);
        }
        cp_commit();
        const uint32_t ab = smb + (ch & 3) * STAGE_BYTES;
        const uint32_t bb = ab + 8192;
#pragma unroll
        for (int j = 0; j < 2; j++) {
            uint32_t aF[2][4], bF[4][4];
#pragma unroll
            for (int mt = 0; mt < 2; mt++) LDSM4(aF[mt], ab + aoffj[j] + mt * 1024);
#pragma unroll
            for (int np = 0; np < 4; np++) LDSM4(bF[np], bb + boffj[j] + np * 1024);
#pragma unroll
            for (int mt = 0; mt < 2; mt++)
#pragma unroll
                for (int n = 0; n < 8; n++)
                    mma_h(acc[mt][n], aF[mt],
                          bF[n >> 1][(n & 1) * 2], bF[n >> 1][(n & 1) * 2 + 1]);
        }
    }

    // ---- epilogue (all paths write fp16)
    if (EPI >= 4) {
#pragma unroll
        for (int n = 0; n < 8; n++) {
            const int col = warpN + n * 8 + 2 * t;
            float s0 = 1.f, s1 = 1.f;
            if (EPI == 5) {
                float2 sp = *(const float2*)(scale + col);
                s0 = sp.x; s1 = sp.y;
            }
#pragma unroll
            for (int mt = 0; mt < 2; mt++) {
                int r = m0 + warpM + mt * 16 + g;
                if (r < Mcnt)
                    *(__half2*)(Cout + (size_t)r * ldc + col) =
                        __floats2half2_rn(acc[mt][n][0] * s0, acc[mt][n][1] * s1);
                if (r + 8 < Mcnt)
                    *(__half2*)(Cout + (size_t)(r + 8) * ldc + col) =
                        __floats2half2_rn(acc[mt][n][2] * s0, acc[mt][n][3] * s1);
            }
        }
    } else {
#pragma unroll
        for (int n = 0; n < 8; n++) {
            const int colB = warpN + n * 8 + 2 * t;   // even col = gate, odd = up
            float sg = 1.f, su = 1.f;
            if (EPI == 3) {
                float2 sp = *(const float2*)(scale + colB);
                sg = sp.x; su = sp.y;
            }
            const int oc = colB >> 1;
#pragma unroll
            for (int mt = 0; mt < 2; mt++) {
                int r = m0 + warpM + mt * 16 + g;
                if (r < Mcnt) {
                    float gg = acc[mt][n][0] * sg, uu = acc[mt][n][1] * su;
                    Cout[(size_t)r * ldc + oc] =
                        __float2half_rn(gg * uu / (1.f + __expf(-gg)));
                }
                if (r + 8 < Mcnt) {
                    float gg = acc[mt][n][2] * sg, uu = acc[mt][n][3] * su;
                    Cout[(size_t)(r + 8) * ldc + oc] =
                        __float2half_rn(gg * uu / (1.f + __expf(-gg)));
                }
            }
        }
    }
}

// ---------------- merged GEMM kernels ---------------------------------------
// mlp1: [0,512) = shared gateup (32 n x 16 m); [512,1536) = expert gu (8e x 16m x 8n)
__global__ __launch_bounds__(256, 2)
void k_mlp1() {
    int id = blockIdx.x;
    if (id < 512) {
        int n0 = (id & 31) * 128;
        int m0 = (id >> 5) * 128;
        gemm_h<false, 2>(g_xh, 0, TTOK, DMODEL,
                         g_wgu + (size_t)n0 * DMODEL, 0,
                         g_act1h + (n0 >> 1), DFS, m0);
    } else {
        id -= 512;
        int e = id >> 7, rem = id & 127;
        int nt = rem & 7, mt = rem >> 3;
        int cnt = g_cnt[e];
        int m0 = mt * 128;
        if (m0 >= cnt) return;
        int n0 = nt * 128;
        gemm_h<true, 3>(g_xh, g_tok + e * MAXPE, cnt, DMODEL,
                        g_egu + ((size_t)e * 2 * DFE + n0) * DMODEL,
                        g_sgu + e * 2 * DFE + n0,
                        g_act2h + (size_t)e * MAXPE * DFE + (n0 >> 1), DFE, m0);
    }
}

// mlp2: [0,128) = shared down (8 n x 16 m); [128,1152) = expert down
__global__ __launch_bounds__(256, 2)
void k_mlp2(const float* __restrict__ ds) {
    int id = blockIdx.x;
    if (id < 128) {
        int n0 = (id & 7) * 128;
        int m0 = (id >> 3) * 128;
        gemm_h<false, 4>(g_act1h, 0, TTOK, DFS,
                         g_wdh + (size_t)n0 * DFS, 0,
                         g_shh + n0, DMODEL, m0);
    } else {
        id -= 128;
        int e = id >> 7, rem = id & 127;
        int nt = rem & 7, mt = rem >> 3;
        int cnt = g_cnt[e];
        int m0 = mt * 128;
        if (m0 >= cnt) return;
        int n0 = nt * 128;
        gemm_h<false, 5>(g_act2h + (size_t)e * MAXPE * DFE, 0, cnt, DFE,
                         g_edh + ((size_t)e * DMODEL + n0) * DFE,
                         ds + e * DMODEL + n0,
                         g_eoh + (size_t)e * MAXPE * DMODEL + n0, DMODEL, m0);
    }
}

// ---------------- mega conversion kernel ------------------------------------
#define NX4   (TTOK * DMODEL / 4)          // 524288
#define NGU4  (DFS * DMODEL / 4)           // 524288
#define ND4   (DMODEL * DFS / 4)           // 524288
#define NEGU4 (NEXP * DFE * DMODEL / 4)    // 1048576
#define NED4  (NEXP * DMODEL * DFE / 4)    // 1048576
#define NSC4  (NEXP * DFE / 4)             // 1024
#define CB0  NX4
#define CB1  (CB0 + NGU4)
#define CB2  (CB1 + NGU4)
#define CB3  (CB2 + ND4)
#define CB4  (CB3 + NEGU4)
#define CB5  (CB4 + NEGU4)
#define CB6  (CB5 + NED4)
#define CB7  (CB6 + 2 * NSC4)
#define CONV_GRID ((CB7 + 1023) / 1024)

__device__ __forceinline__ void wh4f(__half* d, size_t o4, float4 v) {
    ((__half2*)d)[o4 * 2]     = __floats2half2_rn(v.x, v.y);
    ((__half2*)d)[o4 * 2 + 1] = __floats2half2_rn(v.z, v.w);
}
__device__ __forceinline__ void wh4i(__half* d, size_t o4, int4 v) {
    ((__half2*)d)[o4 * 2]     = __floats2half2_rn((float)v.x, (float)v.y);
    ((__half2*)d)[o4 * 2 + 1] = __floats2half2_rn((float)v.z, (float)v.w);
}

__global__ void k_convert(const float* __restrict__ x,
                          const float* __restrict__ shg,
                          const float* __restrict__ shu,
                          const float* __restrict__ shd,
                          const int* __restrict__ gq,
                          const int* __restrict__ uq,
                          const int* __restrict__ dq,
                          const float* __restrict__ gs,
                          const float* __restrict__ us) {
    if (blockIdx.x == 0 && threadIdx.x < NEXP) g_cnt[threadIdx.x] = 0;
    int i0 = blockIdx.x * 1024 + threadIdx.x;
#pragma unroll
    for (int u = 0; u < 4; u++) {
        int i = i0 + u * 256;
        if (i < CB0) {
            wh4f(g_xh, i, ((const float4*)x)[i]);
        } else if (i < CB1) {
            int j = i - CB0;
            int r = j >> 8, c = j & 255;
            wh4f(g_wgu, (size_t)(2 * r) * 256 + c, ((const float4*)shg)[j]);
        } else if (i < CB2) {
            int j = i - CB1;
            int r = j >> 8, c = j & 255;
            wh4f(g_wgu, (size_t)(2 * r + 1) * 256 + c, ((const float4*)shu)[j]);
        } else if (i < CB3) {
            int j = i - CB2;
            wh4f(g_wdh, j, ((const float4*)shd)[j]);
        } else if (i < CB4) {
            int j = i - CB3;
            int r = j >> 8, c = j & 255;
            int e = r >> 9, f = r & 511;
            wh4i(g_egu, (size_t)(e * 1024 + 2 * f) * 256 + c, ((const int4*)gq)[j]);
        } else if (i < CB5) {
            int j = i - CB4;
            int r = j >> 8, c = j & 255;
            int e = r >> 9, f = r & 511;
            wh4i(g_egu, (size_t)(e * 1024 + 2 * f + 1) * 256 + c, ((const int4*)uq)[j]);
        } else if (i < CB6) {
            int j = i - CB5;
            wh4i(g_edh, j, ((const int4*)dq)[j]);
        } else if (i < CB7) {
            int j = i - CB6;
            const float* src = (j < NSC4) ? gs : us;
            int off = (j < NSC4) ? 0 : 1;
            if (j >= NSC4) j -= NSC4;
#pragma unroll
            for (int z = 0; z < 4; z++) {
                int idx = 4 * j + z;
                int e = idx >> 9, f = idx & 511;
                g_sgu[e * 1024 + 2 * f + off] = src[idx];
            }
        }
    }
}

// ---------------- router ----------------------------------------------------
__global__ void k_router(const float* __restrict__ x,
                         const float* __restrict__ rw,
                         const float* __restrict__ alpha) {
    int warp = (blockIdx.x * blockDim.x + threadIdx.x) >> 5;
    int lane = threadIdx.x & 31;
    if (warp >= TTOK) return;
    const float* xr = x + (size_t)warp * DMODEL;
    float acc[NEXP];
#pragma unroll
    for (int e = 0; e < NEXP; e++) acc[e] = 0.f;
    for (int d = lane; d < DMODEL; d += 32) {
        float xv = xr[d];
#pragma unroll
        for (int e = 0; e < NEXP; e++) acc[e] += xv * rw[e * DMODEL + d];
    }
#pragma unroll
    for (int e = 0; e < NEXP; e++)
#pragma unroll
        for (int off = 16; off; off >>= 1)
            acc[e] += __shfl_xor_sync(0xffffffffu, acc[e], off);
    if (lane == 0) {
        int e0 = 0; float v0 = acc[0];
#pragma unroll
        for (int e = 1; e < NEXP; e++) if (acc[e] > v0) { v0 = acc[e]; e0 = e; }
        int e1 = -1; float v1 = -3.4e38f;
#pragma unroll
        for (int e = 0; e < NEXP; e++) if (e != e0 && acc[e] > v1) { v1 = acc[e]; e1 = e; }
        float w0 = 1.f / (1.f + __expf(v1 - v0));
        float w1 = 1.f - w0;
        float c0 = w0 * alpha[e0];
        float c1 = w1 * alpha[e1];
        int p0 = atomicAdd(&g_cnt[e0], 1);
        int p1 = atomicAdd(&g_cnt[e1], 1);
        g_tok[e0 * MAXPE + p0] = warp;
        g_tok[e1 * MAXPE + p1] = warp;
        g_slot0[warp] = e0 * MAXPE + p0;
        g_slot1[warp] = e1 * MAXPE + p1;
        g_c0[warp] = c0;
        g_c1[warp] = c1;
        g_cs[warp] = 1.f - c0 - c1;
    }
}

// ---------------- combine ----------------------------------------------------
__global__ void k_combine(float* __restrict__ out) {
    int tok = blockIdx.x;
    int c = threadIdx.x;                                // 256 threads x 4 elems
    float cs = g_cs[tok], c0 = g_c0[tok], c1 = g_c1[tok];
    size_t s0 = (size_t)g_slot0[tok] * DMODEL;
    size_t s1 = (size_t)g_slot1[tok] * DMODEL;
    const __half2* shp = (const __half2*)&g_shh[(size_t)tok * DMODEL + c * 4];
    const __half2* ap  = (const __half2*)&g_eoh[s0 + c * 4];
    const __half2* bp  = (const __half2*)&g_eoh[s1 + c * 4];
    float2 sh0 = __half22float2(shp[0]), sh1 = __half22float2(shp[1]);
    float2 a0  = __half22float2(ap[0]),  a1  = __half22float2(ap[1]);
    float2 b0  = __half22float2(bp[0]),  b1  = __half22float2(bp[1]);
    float4 o;
    o.x = cs * sh0.x + c0 * a0.x + c1 * b0.x;
    o.y = cs * sh0.y + c0 * a0.y + c1 * b0.y;
    o.z = cs * sh1.x + c0 * a1.x + c1 * b1.x;
    o.w = cs * sh1.y + c0 * a1.y + c1 * b1.y;
    *(float4*)&out[(size_t)tok * DMODEL + c * 4] = o;
}

// ---------------- launch ----------------------------------------------------
extern "C" void kernel_launch(void* const* d_in, const int* in_sizes, int n_in,
                              void* d_out, int out_size) {
    const float *x, *rw, *shg, *shu, *shd, *gs, *us, *ds, *al;
    const int *gq, *uq, *dq;
    if (in_sizes[0] == NEXP) {
        al  = (const float*)d_in[0];
        dq  = (const int*)  d_in[1];
        ds  = (const float*)d_in[2];
        gq  = (const int*)  d_in[3];
        gs  = (const float*)d_in[4];
        rw  = (const float*)d_in[5];
        shd = (const float*)d_in[6];
        shg = (const float*)d_in[7];
        shu = (const float*)d_in[8];
        uq  = (const int*)  d_in[10];
        us  = (const float*)d_in[11];
        x   = (const float*)d_in[12];
    } else {
        x   = (const float*)d_in[0];
        rw  = (const float*)d_in[1];
        shg = (const float*)d_in[2];
        shu = (const float*)d_in[3];
        shd = (const float*)d_in[4];
        gs  = (const float*)d_in[5];
        us  = (const float*)d_in[6];
        ds  = (const float*)d_in[7];
        al  = (const float*)d_in[8];
        gq  = (const int*)  d_in[9];
        uq  = (const int*)  d_in[10];
        dq  = (const int*)  d_in[11];
    }
    float* out = (float*)d_out;

    static int attr_done = 0;
    if (!attr_done) {
        cudaFuncSetAttribute(k_mlp1, cudaFuncAttributeMaxDynamicSharedMemorySize, SMEM_DYN);
        cudaFuncSetAttribute(k_mlp2, cudaFuncAttributeMaxDynamicSharedMemorySize, SMEM_DYN);
        attr_done = 1;
    }

    k_convert<<<CONV_GRID, 256>>>(x, shg, shu, shd, gq, uq, dq, gs, us);
    k_router<<<TTOK / 8, 256>>>(x, rw, al);
    k_mlp1<<<1536, 256, SMEM_DYN>>>();
    k_mlp2<<<1152, 256, SMEM_DYN>>>(ds);
    k_combine<<<TTOK, 256>>>(out);
}

// round 14
// speedup vs baseline: 5.5024x; 1.0302x over previous
#include <cuda_runtime.h>
#include <cuda_fp16.h>
#include <cstdint>

#define TTOK   2048
#define DMODEL 1024
#define DFS    2048
#define DFE    512
#define NEXP   8
#define MAXPE  2048

typedef unsigned long long u64;

// ---------------- scratch (device globals; no allocation allowed) ----------
__device__ __half g_xh   [TTOK * DMODEL];            // fp16 x
__device__ __half g_wgu  [2 * DFS * DMODEL];         // interleaved gate/up shared weights
__device__ __half g_wdh  [DMODEL * DFS];             // shared down weights
__device__ __half g_egu  [NEXP * 2 * DFE * DMODEL];  // interleaved expert gate/up (fp16)
__device__ __half g_edh  [NEXP * DMODEL * DFE];      // expert down (fp16)
__device__ __half g_act1h[TTOK * DFS];               // shared swiglu out (fp16)
__device__ __half g_act2h[NEXP * MAXPE * DFE];       // expert swiglu out (fp16)
__device__ __half g_shh  [TTOK * DMODEL];            // shared MLP out (fp16)
__device__ __half g_eoh  [NEXP * MAXPE * DMODEL];    // expert out (fp16)
__device__ float  g_sgu  [NEXP * 2 * DFE];           // interleaved gate_s/up_s
__device__ int    g_cnt  [NEXP];                     // zero at start (.bss / k_combine)
__device__ int    g_tok  [NEXP * MAXPE];
__device__ int    g_slot0[TTOK];
__device__ int    g_slot1[TTOK];
__device__ float  g_c0[TTOK];
__device__ float  g_c1[TTOK];
__device__ float  g_cs[TTOK];

// ---------------- PTX helpers ----------------------------------------------
__device__ __forceinline__ void cp16(uint32_t dst, const void* src) {
    asm volatile("cp.async.cg.shared.global [%0], [%1], 16;" :: "r"(dst), "l"(src));
}
__device__ __forceinline__ void cp_commit() {
    asm volatile("cp.async.commit_group;" ::: "memory");
}
__device__ __forceinline__ void cp_wait1() {
    asm volatile("cp.async.wait_group 1;" ::: "memory");
}
#define LDSM4(R, addr) \
    asm volatile("ldmatrix.sync.aligned.m8n8.x4.shared.b16 {%0,%1,%2,%3}, [%4];" \
                 : "=r"((R)[0]), "=r"((R)[1]), "=r"((R)[2]), "=r"((R)[3]) \
                 : "r"(addr))
__device__ __forceinline__ void mma_h(float* c, const uint32_t* a,
                                      uint32_t b0, uint32_t b1) {
    asm volatile(
        "mma.sync.aligned.m16n8k16.row.col.f32.f16.f16.f32 "
        "{%0,%1,%2,%3}, {%4,%5,%6,%7}, {%8,%9}, {%0,%1,%2,%3};"
        : "+f"(c[0]), "+f"(c[1]), "+f"(c[2]), "+f"(c[3])
        : "r"(a[0]), "r"(a[1]), "r"(a[2]), "r"(a[3]), "r"(b0), "r"(b1));
}

#define STAGE_BYTES 32768       // A 16KB + B 16KB per stage (BK=64 fp16)
#define NSTAGE      3
#define SMEM_DYN    (STAGE_BYTES * NSTAGE)   // 96KB

// ---------------- fp16 mma GEMM ---------------------------------------------
// C[m,n] = sum_k A[m,k]*B[n,k]; 128x128 tile, BK=64, 256 threads (8 warps,
// warp tile 32x64), 3-stage cp.async pipeline, 2 CTAs/SM.
// EPI: 2 = swiglu->fp16, 3 = swiglu*scale->fp16, 4 = ->fp16, 5 = scale->fp16
template<bool GATHER, int EPI>
__device__ __forceinline__ void gemm_h(
    const __half* __restrict__ A, const int* __restrict__ list,
    int Mcnt, int K,
    const __half* __restrict__ B,
    const float* __restrict__ scale,
    __half* __restrict__ Cout, int ldc, int m0)
{
    extern __shared__ char smc[];
    const uint32_t smb = (uint32_t)__cvta_generic_to_shared(smc);
    const int tid  = threadIdx.x;
    const int wid  = tid >> 5;
    const int lane = tid & 31;
    const int g    = lane >> 2;
    const int t    = lane & 3;
    const int warpM = (wid & 3) * 32;
    const int warpN = (wid >> 2) * 64;

    // staging: thread covers half of row (tid>>1): slots sh2*4 .. sh2*4+3 (16B each)
    const int srow = tid >> 1;
    const int sh2  = tid & 1;
    int ar = m0 + srow;
    if (ar >= Mcnt) ar = Mcnt - 1;
    const char* arow = (const char*)(A + (size_t)(GATHER ? list[ar] : ar) * K);
    const char* brow = (const char*)(B + (size_t)srow * K);
    const uint32_t rsw  = (uint32_t)(srow & 7);
    const uint32_t aDst = smb + srow * 128;
    const uint32_t bDst = smb + 16384 + srow * 128;

    // ldmatrix per-lane offsets (8 slots of 16B per 128B row, slot ^= row&7)
    const int q  = lane >> 3;
    const int rr = lane & 7;
    const int arow0 = warpM + (q & 1) * 8 + rr;
    const int brow0 = warpN + (q >> 1) * 8 + rr;
    const uint32_t qa = (uint32_t)(q >> 1);
    const uint32_t qb = (uint32_t)(q & 1);
    const uint32_t asw = (uint32_t)(arow0 & 7);
    const uint32_t bsw = (uint32_t)(brow0 & 7);
    uint32_t aoffj[4], boffj[4];
#pragma unroll
    for (int j = 0; j < 4; j++) {
        aoffj[j] = (uint32_t)(arow0 * 128) + (((2u * j + qa) ^ asw) << 4);
        boffj[j] = 16384u + (uint32_t)(brow0 * 128) + (((2u * j + qb) ^ bsw) << 4);
    }

    float acc[2][8][4];
#pragma unroll
    for (int m = 0; m < 2; m++)
#pragma unroll
        for (int n = 0; n < 8; n++)
#pragma unroll
            for (int z = 0; z < 4; z++) acc[m][n][z] = 0.f;

    const int nch = K >> 6;   // BK=64

#define STAGE_CHUNK(CH) do {                                                  \
        const uint32_t sb_ = (uint32_t)(((CH) % NSTAGE) * STAGE_BYTES);       \
        const int kb_ = (CH) * 128;                                           \
        _Pragma("unroll")                                                     \
        for (int c_ = 0; c_ < 4; c_++) {                                      \
            uint32_t sl_ = (uint32_t)(sh2 * 4 + c_);                          \
            cp16(aDst + sb_ + ((sl_ ^ rsw) << 4), arow + kb_ + sl_ * 16);     \
            cp16(bDst + sb_ + ((sl_ ^ rsw) << 4), brow + kb_ + sl_ * 16);     \
        }                                                                     \
    } while (0)

    // prologue: stage chunks 0,1
    STAGE_CHUNK(0); cp_commit();
    STAGE_CHUNK(1); cp_commit();
    cp_wait1();
    __syncthreads();

    for (int ch = 0; ch < nch; ch++) {
        const uint32_t ab = smb + (uint32_t)((ch % NSTAGE) * STAGE_BYTES);
#pragma unroll
        for (int j = 0; j < 4; j++) {
            uint32_t aF[2][4], bF[4][4];
#pragma unroll
            for (int mt = 0; mt < 2; mt++) LDSM4(aF[mt], ab + aoffj[j] + mt * 2048);
#pragma unroll
            for (int np = 0; np < 4; np++) LDSM4(bF[np], ab + boffj[j] + np * 2048);
#pragma unroll
            for (int mt = 0; mt < 2; mt++)
#pragma unroll
                for (int n = 0; n < 8; n++)
                    mma_h(acc[mt][n], aF[mt],
                          bF[n >> 1][(n & 1) * 2], bF[n >> 1][(n & 1) * 2 + 1]);
        }
        if (ch + 1 < nch) {
            if (ch + 2 < nch) STAGE_CHUNK(ch + 2);
            cp_commit();
            cp_wait1();
            __syncthreads();
        }
    }
#undef STAGE_CHUNK

    // ---- epilogue (all paths write fp16)
    if (EPI >= 4) {
#pragma unroll
        for (int n = 0; n < 8; n++) {
            const int col = warpN + n * 8 + 2 * t;
            float s0 = 1.f, s1 = 1.f;
            if (EPI == 5) {
                float2 sp = *(const float2*)(scale + col);
                s0 = sp.x; s1 = sp.y;
            }
#pragma unroll
            for (int mt = 0; mt < 2; mt++) {
                int r = m0 + warpM + mt * 16 + g;
                if (r < Mcnt)
                    *(__half2*)(Cout + (size_t)r * ldc + col) =
                        __floats2half2_rn(acc[mt][n][0] * s0, acc[mt][n][1] * s1);
                if (r + 8 < Mcnt)
                    *(__half2*)(Cout + (size_t)(r + 8) * ldc + col) =
                        __floats2half2_rn(acc[mt][n][2] * s0, acc[mt][n][3] * s1);
            }
        }
    } else {
#pragma unroll
        for (int n = 0; n < 8; n++) {
            const int colB = warpN + n * 8 + 2 * t;   // even col = gate, odd = up
            float sg = 1.f, su = 1.f;
            if (EPI == 3) {
                float2 sp = *(const float2*)(scale + colB);
                sg = sp.x; su = sp.y;
            }
            const int oc = colB >> 1;
#pragma unroll
            for (int mt = 0; mt < 2; mt++) {
                int r = m0 + warpM + mt * 16 + g;
                if (r < Mcnt) {
                    float gg = acc[mt][n][0] * sg, uu = acc[mt][n][1] * su;
                    Cout[(size_t)r * ldc + oc] =
                        __float2half_rn(gg * uu / (1.f + __expf(-gg)));
                }
                if (r + 8 < Mcnt) {
                    float gg = acc[mt][n][2] * sg, uu = acc[mt][n][3] * su;
                    Cout[(size_t)(r + 8) * ldc + oc] =
                        __float2half_rn(gg * uu / (1.f + __expf(-gg)));
                }
            }
        }
    }
}

// ---------------- merged GEMM kernels ---------------------------------------
// mlp1: [0,512) = shared gateup (32 n x 16 m); [512,1536) = expert gu
__global__ __launch_bounds__(256, 2)
void k_mlp1() {
    int id = blockIdx.x;
    if (id < 512) {
        int n0 = (id & 31) * 128;
        int m0 = (id >> 5) * 128;
        gemm_h<false, 2>(g_xh, 0, TTOK, DMODEL,
                         g_wgu + (size_t)n0 * DMODEL, 0,
                         g_act1h + (n0 >> 1), DFS, m0);
    } else {
        id -= 512;
        int e = id >> 7, rem = id & 127;
        int nt = rem & 7, mt = rem >> 3;
        int cnt = g_cnt[e];
        int m0 = mt * 128;
        if (m0 >= cnt) return;
        int n0 = nt * 128;
        gemm_h<true, 3>(g_xh, g_tok + e * MAXPE, cnt, DMODEL,
                        g_egu + ((size_t)e * 2 * DFE + n0) * DMODEL,
                        g_sgu + e * 2 * DFE + n0,
                        g_act2h + (size_t)e * MAXPE * DFE + (n0 >> 1), DFE, m0);
    }
}

// mlp2: [0,128) = shared down (8 n x 16 m); [128,1152) = expert down
__global__ __launch_bounds__(256, 2)
void k_mlp2(const float* __restrict__ ds) {
    int id = blockIdx.x;
    if (id < 128) {
        int n0 = (id & 7) * 128;
        int m0 = (id >> 3) * 128;
        gemm_h<false, 4>(g_act1h, 0, TTOK, DFS,
                         g_wdh + (size_t)n0 * DFS, 0,
                         g_shh + n0, DMODEL, m0);
    } else {
        id -= 128;
        int e = id >> 7, rem = id & 127;
        int nt = rem & 7, mt = rem >> 3;
        int cnt = g_cnt[e];
        int m0 = mt * 128;
        if (m0 >= cnt) return;
        int n0 = nt * 128;
        gemm_h<false, 5>(g_act2h + (size_t)e * MAXPE * DFE, 0, cnt, DFE,
                         g_edh + ((size_t)e * DMODEL + n0) * DFE,
                         ds + e * DMODEL + n0,
                         g_eoh + (size_t)e * MAXPE * DMODEL + n0, DMODEL, m0);
    }
}

// ---------------- mega conversion + router kernel ----------------------------
#define NX4   (TTOK * DMODEL / 4)
#define NGU4  (DFS * DMODEL / 4)
#define ND4   (DMODEL * DFS / 4)
#define NEGU4 (NEXP * DFE * DMODEL / 4)
#define NED4  (NEXP * DMODEL * DFE / 4)
#define NSC4  (NEXP * DFE / 4)
#define CB0  NX4
#define CB1  (CB0 + NGU4)
#define CB2  (CB1 + NGU4)
#define CB3  (CB2 + ND4)
#define CB4  (CB3 + NEGU4)
#define CB5  (CB4 + NEGU4)
#define CB6  (CB5 + NED4)
#define CB7  (CB6 + 2 * NSC4)
#define CONV_GRID ((CB7 + 1023) / 1024)
#define ROUT_GRID (TTOK / 8)

__device__ __forceinline__ void wh4f(__half* d, size_t o4, float4 v) {
    ((__half2*)d)[o4 * 2]     = __floats2half2_rn(v.x, v.y);
    ((__half2*)d)[o4 * 2 + 1] = __floats2half2_rn(v.z, v.w);
}
__device__ __forceinline__ void wh4i(__half* d, size_t o4, int4 v) {
    ((__half2*)d)[o4 * 2]     = __floats2half2_rn((float)v.x, (float)v.y);
    ((__half2*)d)[o4 * 2 + 1] = __floats2half2_rn((float)v.z, (float)v.w);
}

__global__ void k_convert(const float* __restrict__ x,
                          const float* __restrict__ shg,
                          const float* __restrict__ shu,
                          const float* __restrict__ shd,
                          const int* __restrict__ gq,
                          const int* __restrict__ uq,
                          const int* __restrict__ dq,
                          const float* __restrict__ gs,
                          const float* __restrict__ us,
                          const float* __restrict__ rw,
                          const float* __restrict__ alpha) {
    if (blockIdx.x >= CONV_GRID) {
        // ---- router part (g_cnt pre-zeroed: .bss on first call, k_combine after)
        int bid = blockIdx.x - CONV_GRID;
        int warp = (bid * 256 + threadIdx.x) >> 5;
        int lane = threadIdx.x & 31;
        if (warp >= TTOK) return;
        const float* xr = x + (size_t)warp * DMODEL;
        float acc[NEXP];
#pragma unroll
        for (int e = 0; e < NEXP; e++) acc[e] = 0.f;
        for (int d = lane; d < DMODEL; d += 32) {
            float xv = xr[d];
#pragma unroll
            for (int e = 0; e < NEXP; e++) acc[e] += xv * rw[e * DMODEL + d];
        }
#pragma unroll
        for (int e = 0; e < NEXP; e++)
#pragma unroll
            for (int off = 16; off; off >>= 1)
                acc[e] += __shfl_xor_sync(0xffffffffu, acc[e], off);
        if (lane == 0) {
            int e0 = 0; float v0 = acc[0];
#pragma unroll
            for (int e = 1; e < NEXP; e++) if (acc[e] > v0) { v0 = acc[e]; e0 = e; }
            int e1 = -1; float v1 = -3.4e38f;
#pragma unroll
            for (int e = 0; e < NEXP; e++) if (e != e0 && acc[e] > v1) { v1 = acc[e]; e1 = e; }
            float w0 = 1.f / (1.f + __expf(v1 - v0));
            float w1 = 1.f - w0;
            float c0 = w0 * alpha[e0];
            float c1 = w1 * alpha[e1];
            int p0 = atomicAdd(&g_cnt[e0], 1);
            int p1 = atomicAdd(&g_cnt[e1], 1);
            g_tok[e0 * MAXPE + p0] = warp;
            g_tok[e1 * MAXPE + p1] = warp;
            g_slot0[warp] = e0 * MAXPE + p0;
            g_slot1[warp] = e1 * MAXPE + p1;
            g_c0[warp] = c0;
            g_c1[warp] = c1;
            g_cs[warp] = 1.f - c0 - c1;
        }
        return;
    }
    // ---- conversion part
    int i0 = blockIdx.x * 1024 + threadIdx.x;
#pragma unroll
    for (int u = 0; u < 4; u++) {
        int i = i0 + u * 256;
        if (i < CB0) {
            wh4f(g_xh, i, ((const float4*)x)[i]);
        } else if (i < CB1) {
            int j = i - CB0;
            int r = j >> 8, c = j & 255;
            wh4f(g_wgu, (size_t)(2 * r) * 256 + c, ((const float4*)shg)[j]);
        } else if (i < CB2) {
            int j = i - CB1;
            int r = j >> 8, c = j & 255;
            wh4f(g_wgu, (size_t)(2 * r + 1) * 256 + c, ((const float4*)shu)[j]);
        } else if (i < CB3) {
            int j = i - CB2;
            wh4f(g_wdh, j, ((const float4*)shd)[j]);
        } else if (i < CB4) {
            int j = i - CB3;
            int r = j >> 8, c = j & 255;
            int e = r >> 9, f = r & 511;
            wh4i(g_egu, (size_t)(e * 1024 + 2 * f) * 256 + c, ((const int4*)gq)[j]);
        } else if (i < CB5) {
            int j = i - CB4;
            int r = j >> 8, c = j & 255;
            int e = r >> 9, f = r & 511;
            wh4i(g_egu, (size_t)(e * 1024 + 2 * f + 1) * 256 + c, ((const int4*)uq)[j]);
        } else if (i < CB6) {
            int j = i - CB5;
            wh4i(g_edh, j, ((const int4*)dq)[j]);
        } else if (i < CB7) {
            int j = i - CB6;
            const float* src = (j < NSC4) ? gs : us;
            int off = (j < NSC4) ? 0 : 1;
            if (j >= NSC4) j -= NSC4;
#pragma unroll
            for (int z = 0; z < 4; z++) {
                int idx = 4 * j + z;
                int e = idx >> 9, f = idx & 511;
                g_sgu[e * 1024 + 2 * f + off] = src[idx];
            }
        }
    }
}

// ---------------- combine (+ reset g_cnt for the next call) ------------------
__global__ void k_combine(float* __restrict__ out) {
    int tok = blockIdx.x;
    int c = threadIdx.x;                                // 256 threads x 4 elems
    if (tok == 0 && c < NEXP) g_cnt[c] = 0;
    float cs = g_cs[tok], c0 = g_c0[tok], c1 = g_c1[tok];
    size_t s0 = (size_t)g_slot0[tok] * DMODEL;
    size_t s1 = (size_t)g_slot1[tok] * DMODEL;
    const __half2* shp = (const __half2*)&g_shh[(size_t)tok * DMODEL + c * 4];
    const __half2* ap  = (const __half2*)&g_eoh[s0 + c * 4];
    const __half2* bp  = (const __half2*)&g_eoh[s1 + c * 4];
    float2 sh0 = __half22float2(shp[0]), sh1 = __half22float2(shp[1]);
    float2 a0  = __half22float2(ap[0]),  a1  = __half22float2(ap[1]);
    float2 b0  = __half22float2(bp[0]),  b1  = __half22float2(bp[1]);
    float4 o;
    o.x = cs * sh0.x + c0 * a0.x + c1 * b0.x;
    o.y = cs * sh0.y + c0 * a0.y + c1 * b0.y;
    o.z = cs * sh1.x + c0 * a1.x + c1 * b1.x;
    o.w = cs * sh1.y + c0 * a1.y + c1 * b1.y;
    *(float4*)&out[(size_t)tok * DMODEL + c * 4] = o;
}

// ---------------- launch ----------------------------------------------------
extern "C" void kernel_launch(void* const* d_in, const int* in_sizes, int n_in,
                              void* d_out, int out_size) {
    const float *x, *rw, *shg, *shu, *shd, *gs, *us, *ds, *al;
    const int *gq, *uq, *dq;
    if (in_sizes[0] == NEXP) {
        al  = (const float*)d_in[0];
        dq  = (const int*)  d_in[1];
        ds  = (const float*)d_in[2];
        gq  = (const int*)  d_in[3];
        gs  = (const float*)d_in[4];
        rw  = (const float*)d_in[5];
        shd = (const float*)d_in[6];
        shg = (const float*)d_in[7];
        shu = (const float*)d_in[8];
        uq  = (const int*)  d_in[10];
        us  = (const float*)d_in[11];
        x   = (const float*)d_in[12];
    } else {
        x   = (const float*)d_in[0];
        rw  = (const float*)d_in[1];
        shg = (const float*)d_in[2];
        shu = (const float*)d_in[3];
        shd = (const float*)d_in[4];
        gs  = (const float*)d_in[5];
        us  = (const float*)d_in[6];
        ds  = (const float*)d_in[7];
        al  = (const float*)d_in[8];
        gq  = (const int*)  d_in[9];
        uq  = (const int*)  d_in[10];
        dq  = (const int*)  d_in[11];
    }
    float* out = (float*)d_out;

    static int attr_done = 0;
    if (!attr_done) {
        cudaFuncSetAttribute(k_mlp1, cudaFuncAttributeMaxDynamicSharedMemorySize, SMEM_DYN);
        cudaFuncSetAttribute(k_mlp2, cudaFuncAttributeMaxDynamicSharedMemorySize, SMEM_DYN);
        attr_done = 1;
    }

    k_convert<<<CONV_GRID + ROUT_GRID, 256>>>(x, shg, shu, shd, gq, uq, dq, gs, us, rw, al);
    k_mlp1<<<1536, 256, SMEM_DYN>>>();
    k_mlp2<<<1152, 256, SMEM_DYN>>>(ds);
    k_combine<<<TTOK, 256>>>(out);
}